// round 8
// baseline (speedup 1.0000x reference)
#include <cuda_runtime.h>
#include <cuda_fp16.h>
#include <cstdint>

// ============================================================================
// TwoTowerModel — tower-specialized warps, GEMM1 weights in registers,
// cp.async gather pipeline, mma.sync fp16. (baseline sm_103 ISA)
// ============================================================================

static constexpr int BATCH   = 524288;
static constexpr int TILE    = 128;
static constexpr int NTILES  = BATCH / TILE;   // 4096
static constexpr int THREADS = 256;            // warps 0-3 user, 4-7 item
static constexpr int NCTAS   = 148;

// ---- shared memory layout (bytes) ----
static constexpr int OFF_X32  = 0;             // [tower] f32 gather landing, 32K each
static constexpr int OFF_XF   = 65536;         // [tower] fp16 X, 16K each
static constexpr int OFF_H    = 98304;         // [tower] fp16 H [128][128], 32K each
static constexpr int OFF_UVEC = 163840;        // f32 frag-linear user vecs, 32K
static constexpr int OFF_W2F  = 196608;        // [tower] GEMM2 W frags, 16K each
static constexpr int OFF_B1   = 229376;        // float[2][128]
static constexpr int OFF_B2   = 230400;        // float[2][64]
static constexpr int SMEM_TOTAL = 230912;      // <= 232448

__device__ __forceinline__ uint32_t smem_u32(const void* p) {
    uint32_t a;
    asm("{ .reg .u64 t; cvta.to.shared.u64 t, %1; cvt.u32.u64 %0, t; }" : "=r"(a) : "l"(p));
    return a;
}
__device__ __forceinline__ void mma_f16(float* d, const uint32_t* a, uint32_t b0, uint32_t b1) {
    asm volatile("mma.sync.aligned.m16n8k16.row.col.f32.f16.f16.f32 "
        "{%0,%1,%2,%3}, {%4,%5,%6,%7}, {%8,%9}, {%0,%1,%2,%3};"
        : "+f"(d[0]), "+f"(d[1]), "+f"(d[2]), "+f"(d[3])
        : "r"(a[0]), "r"(a[1]), "r"(a[2]), "r"(a[3]), "r"(b0), "r"(b1));
}
__device__ __forceinline__ void ldm4(uint32_t* a, uint32_t addr) {
    asm volatile("ldmatrix.sync.aligned.m8n8.x4.shared.b16 {%0,%1,%2,%3}, [%4];"
        : "=r"(a[0]), "=r"(a[1]), "=r"(a[2]), "=r"(a[3]) : "r"(addr) : "memory");
}
__device__ __forceinline__ void lds128(uint32_t* q, uint32_t addr) {
    asm volatile("ld.shared.v4.b32 {%0,%1,%2,%3}, [%4];"
        : "=r"(q[0]), "=r"(q[1]), "=r"(q[2]), "=r"(q[3]) : "r"(addr));
}
__device__ __forceinline__ uint32_t packh2(float a, float b) {
    __half2 h = __floats2half2_rn(a, b);
    return *(uint32_t*)&h;
}
#define CP_ASYNC16(dst, src) \
    asm volatile("cp.async.cg.shared.global [%0], [%1], 16;" :: "r"(dst), "l"(src) : "memory")
#define CP_COMMIT() asm volatile("cp.async.commit_group;" ::: "memory")
#define CP_WAIT0()  asm volatile("cp.async.wait_group 0;" ::: "memory")
#define BAR128(id)  asm volatile("bar.sync %0, 128;" :: "r"(id) : "memory")

__global__ __launch_bounds__(THREADS, 1)
void twotower_kernel(
    const int* __restrict__ user_ids, const int* __restrict__ item_ids,
    const float* __restrict__ user_table, const float* __restrict__ item_table,
    const float* __restrict__ uW1, const float* __restrict__ ub1,
    const float* __restrict__ uW2, const float* __restrict__ ub2,
    const float* __restrict__ iW1, const float* __restrict__ ib1,
    const float* __restrict__ iW2, const float* __restrict__ ib2,
    float* __restrict__ out)
{
    extern __shared__ char smem[];
    const uint32_t sb = smem_u32(smem);
    const int tid   = threadIdx.x;
    const int lane  = tid & 31;
    const int tg    = lane & 3;
    const int g     = lane >> 2;
    const int khalf = lane >> 4;
    const int tower = tid >> 7;          // 0=user, 1=item
    const int ttid  = tid & 127;
    const int twid  = ttid >> 5;         // warp within tower, 0..3
    const int row   = ttid;              // gather row ownership

    // ---- stage GEMM2 weight fragments + biases in smem (same packing as R5) ----
    for (int t = 0; t < 2; t++) {
        const float* gW2 = t ? iW2 : uW2;   // [128][64]
        const float* gb1 = t ? ib1 : ub1;
        const float* gb2 = t ? ib2 : ub2;
        for (int p = tid; p < 1024; p += THREADS) {       // kt(8) x ntp(4) x lane(32)
            int kt = p >> 7, ntp = (p >> 5) & 3, ln = p & 31;
            int ltg = ln & 3, lg = ln >> 2;
            int k0 = kt * 16 + ltg * 2;
            uint32_t q[4];
#pragma unroll
            for (int s = 0; s < 2; s++) {
                int n = (2 * ntp + s) * 8 + lg;
                q[2 * s + 0] = packh2(__ldg(gW2 + k0 * 64 + n),       __ldg(gW2 + (k0 + 1) * 64 + n));
                q[2 * s + 1] = packh2(__ldg(gW2 + (k0 + 8) * 64 + n), __ldg(gW2 + (k0 + 9) * 64 + n));
            }
            *((uint4*)(smem + OFF_W2F + t * 16384) + p) = make_uint4(q[0], q[1], q[2], q[3]);
        }
        if (tid < 128) ((float*)(smem + OFF_B1))[t * 128 + tid] = __ldg(gb1 + tid);
        if (tid < 64)  ((float*)(smem + OFF_B2))[t * 64 + tid]  = __ldg(gb2 + tid);
    }

    // ---- GEMM1 weights: resident registers, this warp's 32-col N-slice ----
    uint32_t w1b0[4][4], w1b1[4][4];
    {
        const float* gW1 = tower ? iW1 : uW1;   // [64][128]
#pragma unroll
        for (int kt = 0; kt < 4; kt++)
#pragma unroll
            for (int ntl = 0; ntl < 4; ntl++) {
                int n  = (twid * 4 + ntl) * 8 + g;
                int k0 = kt * 16 + tg * 2;
                w1b0[kt][ntl] = packh2(__ldg(gW1 + k0 * 128 + n),       __ldg(gW1 + (k0 + 1) * 128 + n));
                w1b1[kt][ntl] = packh2(__ldg(gW1 + (k0 + 8) * 128 + n), __ldg(gW1 + (k0 + 9) * 128 + n));
            }
    }
    __syncthreads();

    const int*   myids = tower ? item_ids   : user_ids;
    const float* mytbl = tower ? item_table : user_table;
    const uint32_t x32b = sb + OFF_X32 + (uint32_t)tower * 32768u + (uint32_t)row * 256u;
    const uint32_t xfb  = sb + OFF_XF  + (uint32_t)tower * 16384u;
    const uint32_t hbb  = sb + OFF_H   + (uint32_t)tower * 32768u;
    const uint32_t r15  = (uint32_t)(row & 15), r7 = (uint32_t)(row & 7);
    const int R = twid * 32;             // GEMM2 row base
    const int barid = 1 + tower;

    // ---- prologue: issue tile0 gather, prefetch next id ----
    int tile = blockIdx.x;
    {
        int id0 = __ldg(myids + tile * TILE + row);
        const char* src = (const char*)mytbl + (size_t)(uint32_t)id0 * 256u;
#pragma unroll
        for (int j = 0; j < 16; j++)
            CP_ASYNC16(x32b + (((uint32_t)j ^ r15) << 4), src + j * 16);
        CP_COMMIT();
    }
    int tn0 = tile + (int)gridDim.x; if (tn0 >= NTILES) tn0 = tile;
    int id_nx = __ldg(myids + tn0 * TILE + row);

    for (; tile < NTILES; tile += gridDim.x) {
        const int rowbase = tile * TILE;
        int tnext = tile + (int)gridDim.x;
        if (tnext >= NTILES) tnext = tile;

        // ---- A/B: wait own gather, convert own row f32 -> fp16 ----
        CP_WAIT0();
        {
            uint32_t xo = xfb + (uint32_t)row * 128u;
#pragma unroll
            for (int jj = 0; jj < 8; jj++) {
                float4 qa = *(const float4*)(smem + (x32b - sb) + ((((uint32_t)(2 * jj))     ^ r15) << 4));
                float4 qb = *(const float4*)(smem + (x32b - sb) + ((((uint32_t)(2 * jj + 1)) ^ r15) << 4));
                uint4 o = make_uint4(packh2(qa.x, qa.y), packh2(qa.z, qa.w),
                                     packh2(qb.x, qb.y), packh2(qb.z, qb.w));
                *(uint4*)(smem + (xo - sb) + (((uint32_t)jj ^ r7) << 4)) = o;
            }
        }
        BAR128(barid);                       // C: X fp16 ready tower-wide

        // ---- D: issue next-tile gather + prefetch id after that ----
        {
            const char* src = (const char*)mytbl + (size_t)(uint32_t)id_nx * 256u;
#pragma unroll
            for (int j = 0; j < 16; j++)
                CP_ASYNC16(x32b + (((uint32_t)j ^ r15) << 4), src + j * 16);
            CP_COMMIT();
            int t2 = tnext + (int)gridDim.x; if (t2 >= NTILES) t2 = tnext;
            id_nx = __ldg(myids + t2 * TILE + row);
        }

        // ---- E: GEMM1 over all 128 rows, this warp's 32-col slice; epilogue -> H ----
        {
            const float* b1p = (const float*)(smem + OFF_B1) + tower * 128;
#pragma unroll
            for (int rb = 0; rb < 8; rb++) {
                float acc1[4][4];
#pragma unroll
                for (int i = 0; i < 4; i++)
#pragma unroll
                    for (int j = 0; j < 4; j++) acc1[i][j] = 0.0f;
                int lr = 16 * rb + (lane & 15);
                uint32_t lrb_ = (uint32_t)lr * 128u;
                int lrx = lr & 7;
#pragma unroll
                for (int kt = 0; kt < 4; kt++) {
                    uint32_t A[4];
                    ldm4(A, xfb + lrb_ + ((((uint32_t)(kt * 2 + khalf)) ^ (uint32_t)lrx) << 4));
#pragma unroll
                    for (int ntl = 0; ntl < 4; ntl++)
                        mma_f16(acc1[ntl], A, w1b0[kt][ntl], w1b1[kt][ntl]);
                }
                int rowA = 16 * rb + g, rowB = rowA + 8;
#pragma unroll
                for (int ntl = 0; ntl < 4; ntl++) {
                    int nt = twid * 4 + ntl;
                    int c0 = nt * 8 + tg * 2;
                    float v0 = fmaxf(acc1[ntl][0] + b1p[c0],     0.0f);
                    float v1 = fmaxf(acc1[ntl][1] + b1p[c0 + 1], 0.0f);
                    float v2 = fmaxf(acc1[ntl][2] + b1p[c0],     0.0f);
                    float v3 = fmaxf(acc1[ntl][3] + b1p[c0 + 1], 0.0f);
                    uint32_t hb = hbb + (uint32_t)(nt >> 3) * 16384u;
                    uint32_t cc = (uint32_t)(nt & 7);
                    *(uint32_t*)(smem + (hb - sb) + (uint32_t)rowA * 128u + ((cc ^ (uint32_t)(rowA & 7)) << 4) + (uint32_t)tg * 4) = packh2(v0, v1);
                    *(uint32_t*)(smem + (hb - sb) + (uint32_t)rowB * 128u + ((cc ^ (uint32_t)(rowB & 7)) << 4) + (uint32_t)tg * 4) = packh2(v2, v3);
                }
            }
        }
        BAR128(barid);                       // F: H complete tower-wide

        // ---- G: GEMM2, rows R..R+31, full N=64, weights reused across 2 rowblocks ----
        float acc2[2][8][4];
#pragma unroll
        for (int b = 0; b < 2; b++)
#pragma unroll
            for (int i = 0; i < 8; i++)
#pragma unroll
                for (int j = 0; j < 4; j++) acc2[b][i][j] = 0.0f;
        {
            int lrA = R + (lane & 15), lrB = R + 16 + (lane & 15);
#pragma unroll
            for (int kt = 0; kt < 8; kt++) {
                uint32_t Aa[4], Ab[4];
                uint32_t hc = hbb + (uint32_t)(kt >> 2) * 16384u;
                uint32_t chg = (uint32_t)((kt & 3) * 2 + khalf);
                ldm4(Aa, hc + (uint32_t)lrA * 128u + ((chg ^ (uint32_t)(lrA & 7)) << 4));
                ldm4(Ab, hc + (uint32_t)lrB * 128u + ((chg ^ (uint32_t)(lrB & 7)) << 4));
                uint32_t wb = sb + OFF_W2F + (uint32_t)tower * 16384u + ((uint32_t)(kt * 128 + lane)) * 16u;
#pragma unroll
                for (int ntp = 0; ntp < 4; ntp++) {
                    uint32_t q[4];
                    lds128(q, wb + (uint32_t)ntp * 512u);
                    mma_f16(acc2[0][2 * ntp],     Aa, q[0], q[1]);
                    mma_f16(acc2[0][2 * ntp + 1], Aa, q[2], q[3]);
                    mma_f16(acc2[1][2 * ntp],     Ab, q[0], q[1]);
                    mma_f16(acc2[1][2 * ntp + 1], Ab, q[2], q[3]);
                }
            }
        }

        // ---- epilogue 2: bias + relu + l2norm (both towers) ----
        const float* b2p = (const float*)(smem + OFF_B2) + tower * 64;
        float invA[2], invB[2];
#pragma unroll
        for (int blk = 0; blk < 2; blk++) {
            float ssA = 0.0f, ssB = 0.0f;
#pragma unroll
            for (int nt = 0; nt < 8; nt++) {
                int c0 = nt * 8 + tg * 2;
                acc2[blk][nt][0] = fmaxf(acc2[blk][nt][0] + b2p[c0],     0.0f);
                acc2[blk][nt][1] = fmaxf(acc2[blk][nt][1] + b2p[c0 + 1], 0.0f);
                acc2[blk][nt][2] = fmaxf(acc2[blk][nt][2] + b2p[c0],     0.0f);
                acc2[blk][nt][3] = fmaxf(acc2[blk][nt][3] + b2p[c0 + 1], 0.0f);
                ssA += acc2[blk][nt][0] * acc2[blk][nt][0] + acc2[blk][nt][1] * acc2[blk][nt][1];
                ssB += acc2[blk][nt][2] * acc2[blk][nt][2] + acc2[blk][nt][3] * acc2[blk][nt][3];
            }
            ssA += __shfl_xor_sync(0xffffffffu, ssA, 1);
            ssA += __shfl_xor_sync(0xffffffffu, ssA, 2);
            ssB += __shfl_xor_sync(0xffffffffu, ssB, 1);
            ssB += __shfl_xor_sync(0xffffffffu, ssB, 2);
            invA[blk] = 1.0f / fmaxf(sqrtf(ssA), 1e-12f);
            invB[blk] = 1.0f / fmaxf(sqrtf(ssB), 1e-12f);
        }

        if (tower == 0) {
            // user: normalized vecs -> UVEC (frag-linear [block8][nt8][lane32] float4)
#pragma unroll
            for (int blk = 0; blk < 2; blk++) {
                uint32_t base = (uint32_t)(((twid * 2 + blk) * 8) * 32 + lane) * 16u;
#pragma unroll
                for (int nt = 0; nt < 8; nt++) {
                    float4 v = make_float4(acc2[blk][nt][0] * invA[blk], acc2[blk][nt][1] * invA[blk],
                                           acc2[blk][nt][2] * invB[blk], acc2[blk][nt][3] * invB[blk]);
                    *(float4*)(smem + OFF_UVEC + base + (uint32_t)nt * 512u) = v;
                }
            }
        }
        __syncthreads();                     // H: UVEC ready

        if (tower == 1) {
            // item: dot with UVEC, reduce, store
#pragma unroll
            for (int blk = 0; blk < 2; blk++) {
                uint32_t base = (uint32_t)(((twid * 2 + blk) * 8) * 32 + lane) * 16u;
                float dA = 0.0f, dB = 0.0f;
#pragma unroll
                for (int nt = 0; nt < 8; nt++) {
                    float4 u = *(const float4*)(smem + OFF_UVEC + base + (uint32_t)nt * 512u);
                    dA += u.x * acc2[blk][nt][0] + u.y * acc2[blk][nt][1];
                    dB += u.z * acc2[blk][nt][2] + u.w * acc2[blk][nt][3];
                }
                dA *= invA[blk];
                dB *= invB[blk];
                dA += __shfl_xor_sync(0xffffffffu, dA, 1);
                dA += __shfl_xor_sync(0xffffffffu, dA, 2);
                dB += __shfl_xor_sync(0xffffffffu, dB, 1);
                dB += __shfl_xor_sync(0xffffffffu, dB, 2);
                if (tg == 0) {
                    int rowA = R + 16 * blk + g;
                    out[rowbase + rowA]     = dA;
                    out[rowbase + rowA + 8] = dB;
                }
            }
        }
        __syncthreads();                     // J: UVEC consumed, safe for next tile
    }
}

extern "C" void kernel_launch(void* const* d_in, const int* in_sizes, int n_in,
                              void* d_out, int out_size) {
    const int*   user_ids   = (const int*)d_in[0];
    const int*   item_ids   = (const int*)d_in[1];
    const float* user_table = (const float*)d_in[2];
    const float* item_table = (const float*)d_in[3];
    const float* uW1 = (const float*)d_in[4];
    const float* ub1 = (const float*)d_in[5];
    const float* uW2 = (const float*)d_in[6];
    const float* ub2 = (const float*)d_in[7];
    const float* iW1 = (const float*)d_in[8];
    const float* ib1 = (const float*)d_in[9];
    const float* iW2 = (const float*)d_in[10];
    const float* ib2 = (const float*)d_in[11];
    float* out = (float*)d_out;

    cudaFuncSetAttribute(twotower_kernel, cudaFuncAttributeMaxDynamicSharedMemorySize, SMEM_TOTAL);
    twotower_kernel<<<NCTAS, THREADS, SMEM_TOTAL>>>(
        user_ids, item_ids, user_table, item_table,
        uW1, ub1, uW2, ub2, iW1, ib1, iW2, ib2, out);
}

// round 10
// speedup vs baseline: 1.6918x; 1.6918x over previous
#include <cuda_runtime.h>
#include <cuda_fp16.h>
#include <cstdint>

// ============================================================================
// TwoTowerModel — independent-warp fp16 mma.sync, pipelined gather,
// GEMM1->GEMM2 activation handoff entirely in registers (no H smem roundtrip).
// (baseline sm_103 ISA: no tcgen05 — harness PTX target is sm_103)
// ============================================================================

static constexpr int BATCH   = 524288;
static constexpr int TILE    = 128;
static constexpr int NTILES  = BATCH / TILE;   // 4096
static constexpr int THREADS = 256;            // 8 warps, each owns 16 rows
static constexpr int NCTAS   = 148;

// ---- shared memory layout (bytes) ----
static constexpr int OFF_XU   = 0;             // user emb fp16 [128][64] swizzled, 16K
static constexpr int OFF_XI   = 16384;         // item emb fp16, 16K
static constexpr int OFF_UVEC = 32768;         // normalized user vec f32 [128][64], 32K
static constexpr int OFF_W1F  = 65536;         // W1 frags (nt-paired): [tower]*16K = 32K
static constexpr int OFF_W2F  = 98304;         // W2 frags: 32K
static constexpr int OFF_B1   = 131072;        // float[2][128]
static constexpr int OFF_B2   = 132096;        // float[2][64]
static constexpr int SMEM_TOTAL = 132608;

__device__ __forceinline__ uint32_t smem_u32(const void* p) {
    uint32_t a;
    asm("{ .reg .u64 t; cvta.to.shared.u64 t, %1; cvt.u32.u64 %0, t; }" : "=r"(a) : "l"(p));
    return a;
}
__device__ __forceinline__ void mma_f16(float* d, const uint32_t* a, uint32_t b0, uint32_t b1) {
    asm volatile("mma.sync.aligned.m16n8k16.row.col.f32.f16.f16.f32 "
        "{%0,%1,%2,%3}, {%4,%5,%6,%7}, {%8,%9}, {%0,%1,%2,%3};"
        : "+f"(d[0]), "+f"(d[1]), "+f"(d[2]), "+f"(d[3])
        : "r"(a[0]), "r"(a[1]), "r"(a[2]), "r"(a[3]), "r"(b0), "r"(b1));
}
__device__ __forceinline__ void ldm4(uint32_t* a, uint32_t addr) {
    asm volatile("ldmatrix.sync.aligned.m8n8.x4.shared.b16 {%0,%1,%2,%3}, [%4];"
        : "=r"(a[0]), "=r"(a[1]), "=r"(a[2]), "=r"(a[3]) : "r"(addr) : "memory");
}
__device__ __forceinline__ void lds128(uint32_t* q, uint32_t addr) {
    asm volatile("ld.shared.v4.b32 {%0,%1,%2,%3}, [%4];"
        : "=r"(q[0]), "=r"(q[1]), "=r"(q[2]), "=r"(q[3]) : "r"(addr));
}
__device__ __forceinline__ uint32_t packh2(float a, float b) {
    __half2 h = __floats2half2_rn(a, b);
    return *(uint32_t*)&h;
}

__global__ __launch_bounds__(THREADS, 1)
void twotower_kernel(
    const int* __restrict__ user_ids, const int* __restrict__ item_ids,
    const float* __restrict__ user_table, const float* __restrict__ item_table,
    const float* __restrict__ uW1, const float* __restrict__ ub1,
    const float* __restrict__ uW2, const float* __restrict__ ub2,
    const float* __restrict__ iW1, const float* __restrict__ ib1,
    const float* __restrict__ iW2, const float* __restrict__ ib2,
    float* __restrict__ out)
{
    extern __shared__ char smem[];
    const uint32_t sb = smem_u32(smem);
    const int tid  = threadIdx.x;
    const int wid  = tid >> 5;
    const int lane = tid & 31;
    const int tg   = lane & 3;
    const int g    = lane >> 2;

    // ============ stage weights as nt-paired mma B-fragments (fp16) ====
    for (int t = 0; t < 2; t++) {
        const float* gW1 = t ? iW1 : uW1;   // [64][128] row-major
        const float* gW2 = t ? iW2 : uW2;   // [128][64]
        const float* gb1 = t ? ib1 : ub1;
        const float* gb2 = t ? ib2 : ub2;
        for (int p = tid; p < 1024; p += THREADS) {       // W1: kt(4) x ntp(8) x lane(32)
            int kt = p >> 8, ntp = (p >> 5) & 7, ln = p & 31;
            int ltg = ln & 3, lg = ln >> 2;
            int k0 = kt * 16 + ltg * 2;
            uint32_t q[4];
#pragma unroll
            for (int s = 0; s < 2; s++) {
                int n = (2 * ntp + s) * 8 + lg;
                q[2 * s + 0] = packh2(__ldg(gW1 + k0 * 128 + n),       __ldg(gW1 + (k0 + 1) * 128 + n));
                q[2 * s + 1] = packh2(__ldg(gW1 + (k0 + 8) * 128 + n), __ldg(gW1 + (k0 + 9) * 128 + n));
            }
            *((uint4*)(smem + OFF_W1F + t * 16384) + p) = make_uint4(q[0], q[1], q[2], q[3]);
        }
        for (int p = tid; p < 1024; p += THREADS) {       // W2: kt(8) x ntp(4) x lane(32)
            int kt = p >> 7, ntp = (p >> 5) & 3, ln = p & 31;
            int ltg = ln & 3, lg = ln >> 2;
            int k0 = kt * 16 + ltg * 2;
            uint32_t q[4];
#pragma unroll
            for (int s = 0; s < 2; s++) {
                int n = (2 * ntp + s) * 8 + lg;
                q[2 * s + 0] = packh2(__ldg(gW2 + k0 * 64 + n),       __ldg(gW2 + (k0 + 1) * 64 + n));
                q[2 * s + 1] = packh2(__ldg(gW2 + (k0 + 8) * 64 + n), __ldg(gW2 + (k0 + 9) * 64 + n));
            }
            *((uint4*)(smem + OFF_W2F + t * 16384) + p) = make_uint4(q[0], q[1], q[2], q[3]);
        }
        if (tid < 128) ((float*)(smem + OFF_B1))[t * 128 + tid] = __ldg(gb1 + tid);
        if (tid < 64)  ((float*)(smem + OFF_B2))[t * 64 + tid]  = __ldg(gb2 + tid);
    }
    __syncthreads();

    // per-lane ldmatrix row addressing (X tiles, K=64 -> 2 k-chunks of 8 cols)
    const int lr   = 16 * wid + (lane & 15);
    const int lrx  = lr & 7;
    const uint32_t lrb = (uint32_t)lr * 128;
    const int khalf = lane >> 4;

    // epilogue row pair
    const int rA = 16 * wid + g;
    const int rB = rA + 8;

    // gather mapping: 2 threads per row, warp-local rows
    const int grow  = tid >> 1;
    const int ghalf = tid & 1;

    // ---------------- prologue: prefetch tile0 user rows + item id ----------------
    int tile = blockIdx.x;
    float4 uf4[8];
    {
        int uid = __ldg(user_ids + tile * TILE + grow);
        const float4* usrc = (const float4*)(user_table + (size_t)uid * 64) + ghalf * 8;
#pragma unroll
        for (int j = 0; j < 8; j++) uf4[j] = __ldg(usrc + j);
    }
    int iid_hold = __ldg(item_ids + tile * TILE + grow);

    for (; tile < NTILES; tile += gridDim.x) {
        const int rowbase = tile * TILE;
        int tnext = tile + (int)gridDim.x;
        if (tnext >= NTILES) tnext = tile;   // harmless reload on last iteration

        // ---- 1. convert prefetched user rows -> XU (fp16, SW128) ----
#pragma unroll
        for (int j = 0; j < 4; j++) {
            float4 q0 = uf4[2 * j], q1 = uf4[2 * j + 1];
            uint32_t a = packh2(q0.x, q0.y), b = packh2(q0.z, q0.w);
            uint32_t c = packh2(q1.x, q1.y), d = packh2(q1.z, q1.w);
            uint32_t ch = (uint32_t)(ghalf * 4 + j);
            uint32_t ad = (uint32_t)grow * 128 + ((ch ^ ((uint32_t)grow & 7)) << 4);
            *(uint4*)(smem + OFF_XU + ad) = make_uint4(a, b, c, d);
        }
        __syncwarp();

        // ---- 2. issue item gather LDGs (hide under user GEMM1/2) ----
        float4 if4[8];
        {
            const float4* isrc = (const float4*)(item_table + (size_t)iid_hold * 64) + ghalf * 8;
#pragma unroll
            for (int j = 0; j < 8; j++) if4[j] = __ldg(isrc + j);
        }
        // ---- 3. prefetch next-tile ids ----
        int uid_next = __ldg(user_ids + tnext * TILE + grow);
        int iid_next = __ldg(item_ids + tnext * TILE + grow);

        // ================= USER tower =================
        // ---- GEMM1: D1[16x128] = XU * W1u, K=64 ----
        float acc[16][4];
#pragma unroll
        for (int nt = 0; nt < 16; nt++)
#pragma unroll
            for (int j = 0; j < 4; j++) acc[nt][j] = 0.0f;
#pragma unroll
        for (int kt = 0; kt < 4; kt++) {
            uint32_t A[4];
            uint32_t chg = (uint32_t)(kt * 2 + khalf);
            ldm4(A, sb + OFF_XU + lrb + ((chg ^ (uint32_t)lrx) << 4));
            uint32_t wb = sb + OFF_W1F + ((uint32_t)(kt * 8 * 32 + lane)) * 16;
#pragma unroll
            for (int ntp = 0; ntp < 8; ntp++) {
                uint32_t q[4];
                lds128(q, wb + (uint32_t)ntp * 512);
                mma_f16(acc[2 * ntp],     A, q[0], q[1]);
                mma_f16(acc[2 * ntp + 1], A, q[2], q[3]);
            }
        }
        // ---- epilogue 1 (in-register): bias+relu -> GEMM2 A-frags hfrag[8][4] ----
        // output frag (rows g,g+8 x cols nt*8+2tg,+1) == A-frag of GEMM2 step kt:
        //   a0/a1 from nt=2kt (cols 16kt+2tg), a2/a3 from nt=2kt+1 (cols 16kt+8+2tg)
        uint32_t hfrag[8][4];
        {
            const float* b1p = (const float*)(smem + OFF_B1);
#pragma unroll
            for (int kt = 0; kt < 8; kt++) {
                int ntA = 2 * kt, ntB = 2 * kt + 1;
                int cA = ntA * 8 + tg * 2, cB = ntB * 8 + tg * 2;
                hfrag[kt][0] = packh2(fmaxf(acc[ntA][0] + b1p[cA],     0.0f),
                                      fmaxf(acc[ntA][1] + b1p[cA + 1], 0.0f));
                hfrag[kt][1] = packh2(fmaxf(acc[ntA][2] + b1p[cA],     0.0f),
                                      fmaxf(acc[ntA][3] + b1p[cA + 1], 0.0f));
                hfrag[kt][2] = packh2(fmaxf(acc[ntB][0] + b1p[cB],     0.0f),
                                      fmaxf(acc[ntB][1] + b1p[cB + 1], 0.0f));
                hfrag[kt][3] = packh2(fmaxf(acc[ntB][2] + b1p[cB],     0.0f),
                                      fmaxf(acc[ntB][3] + b1p[cB + 1], 0.0f));
            }
        }

        // ---- 5. convert item rows -> XI ----
#pragma unroll
        for (int j = 0; j < 4; j++) {
            float4 q0 = if4[2 * j], q1 = if4[2 * j + 1];
            uint32_t a = packh2(q0.x, q0.y), b = packh2(q0.z, q0.w);
            uint32_t c = packh2(q1.x, q1.y), d = packh2(q1.z, q1.w);
            uint32_t ch = (uint32_t)(ghalf * 4 + j);
            uint32_t ad = (uint32_t)grow * 128 + ((ch ^ ((uint32_t)grow & 7)) << 4);
            *(uint4*)(smem + OFF_XI + ad) = make_uint4(a, b, c, d);
        }
        __syncwarp();

        // ---- 6. issue next-tile user gather LDGs ----
        {
            const float4* usrc = (const float4*)(user_table + (size_t)uid_next * 64) + ghalf * 8;
#pragma unroll
            for (int j = 0; j < 8; j++) uf4[j] = __ldg(usrc + j);
        }

        // ---- GEMM2 user: D2[16x64] = H * W2u, K=128, A from hfrag ----
        float acc2[8][4];
#pragma unroll
        for (int nt = 0; nt < 8; nt++)
#pragma unroll
            for (int j = 0; j < 4; j++) acc2[nt][j] = 0.0f;
#pragma unroll
        for (int kt = 0; kt < 8; kt++) {
            uint32_t wb = sb + OFF_W2F + ((uint32_t)(kt * 4 * 32 + lane)) * 16;
#pragma unroll
            for (int ntp = 0; ntp < 4; ntp++) {
                uint32_t q[4];
                lds128(q, wb + (uint32_t)ntp * 512);
                mma_f16(acc2[2 * ntp],     hfrag[kt], q[0], q[1]);
                mma_f16(acc2[2 * ntp + 1], hfrag[kt], q[2], q[3]);
            }
        }
        // ---- epilogue 2 user: bias + relu + l2norm -> UVEC smem ----
        {
            const float* b2p = (const float*)(smem + OFF_B2);
            float ssA = 0.0f, ssB = 0.0f;
#pragma unroll
            for (int nt = 0; nt < 8; nt++) {
                int c0 = nt * 8 + tg * 2;
                acc2[nt][0] = fmaxf(acc2[nt][0] + b2p[c0],     0.0f);
                acc2[nt][1] = fmaxf(acc2[nt][1] + b2p[c0 + 1], 0.0f);
                acc2[nt][2] = fmaxf(acc2[nt][2] + b2p[c0],     0.0f);
                acc2[nt][3] = fmaxf(acc2[nt][3] + b2p[c0 + 1], 0.0f);
                ssA += acc2[nt][0] * acc2[nt][0] + acc2[nt][1] * acc2[nt][1];
                ssB += acc2[nt][2] * acc2[nt][2] + acc2[nt][3] * acc2[nt][3];
            }
            ssA += __shfl_xor_sync(0xffffffffu, ssA, 1);
            ssA += __shfl_xor_sync(0xffffffffu, ssA, 2);
            ssB += __shfl_xor_sync(0xffffffffu, ssB, 1);
            ssB += __shfl_xor_sync(0xffffffffu, ssB, 2);
            float invA = 1.0f / fmaxf(sqrtf(ssA), 1e-12f);
            float invB = 1.0f / fmaxf(sqrtf(ssB), 1e-12f);
            // frag-linear UVEC: [wid][nt][lane] float4 = 16B per lane
            uint32_t base = (uint32_t)((wid * 8) * 32 + lane) * 16u;
#pragma unroll
            for (int nt = 0; nt < 8; nt++) {
                float4 v = make_float4(acc2[nt][0] * invA, acc2[nt][1] * invA,
                                       acc2[nt][2] * invB, acc2[nt][3] * invB);
                *(float4*)(smem + OFF_UVEC + base + (uint32_t)nt * 512u) = v;
            }
        }
        __syncwarp();

        // ================= ITEM tower =================
        // ---- GEMM1 item (XI) ----
#pragma unroll
        for (int nt = 0; nt < 16; nt++)
#pragma unroll
            for (int j = 0; j < 4; j++) acc[nt][j] = 0.0f;
#pragma unroll
        for (int kt = 0; kt < 4; kt++) {
            uint32_t A[4];
            uint32_t chg = (uint32_t)(kt * 2 + khalf);
            ldm4(A, sb + OFF_XI + lrb + ((chg ^ (uint32_t)lrx) << 4));
            uint32_t wb = sb + OFF_W1F + 16384u + ((uint32_t)(kt * 8 * 32 + lane)) * 16;
#pragma unroll
            for (int ntp = 0; ntp < 8; ntp++) {
                uint32_t q[4];
                lds128(q, wb + (uint32_t)ntp * 512);
                mma_f16(acc[2 * ntp],     A, q[0], q[1]);
                mma_f16(acc[2 * ntp + 1], A, q[2], q[3]);
            }
        }
        // ---- epilogue 1 item (in-register) -> hfrag ----
        {
            const float* b1p = (const float*)(smem + OFF_B1) + 128;
#pragma unroll
            for (int kt = 0; kt < 8; kt++) {
                int ntA = 2 * kt, ntB = 2 * kt + 1;
                int cA = ntA * 8 + tg * 2, cB = ntB * 8 + tg * 2;
                hfrag[kt][0] = packh2(fmaxf(acc[ntA][0] + b1p[cA],     0.0f),
                                      fmaxf(acc[ntA][1] + b1p[cA + 1], 0.0f));
                hfrag[kt][1] = packh2(fmaxf(acc[ntA][2] + b1p[cA],     0.0f),
                                      fmaxf(acc[ntA][3] + b1p[cA + 1], 0.0f));
                hfrag[kt][2] = packh2(fmaxf(acc[ntB][0] + b1p[cB],     0.0f),
                                      fmaxf(acc[ntB][1] + b1p[cB + 1], 0.0f));
                hfrag[kt][3] = packh2(fmaxf(acc[ntB][2] + b1p[cB],     0.0f),
                                      fmaxf(acc[ntB][3] + b1p[cB + 1], 0.0f));
            }
        }

        // ---- GEMM2 item ----
#pragma unroll
        for (int nt = 0; nt < 8; nt++)
#pragma unroll
            for (int j = 0; j < 4; j++) acc2[nt][j] = 0.0f;
#pragma unroll
        for (int kt = 0; kt < 8; kt++) {
            uint32_t wb = sb + OFF_W2F + 16384u + ((uint32_t)(kt * 4 * 32 + lane)) * 16;
#pragma unroll
            for (int ntp = 0; ntp < 4; ntp++) {
                uint32_t q[4];
                lds128(q, wb + (uint32_t)ntp * 512);
                mma_f16(acc2[2 * ntp],     hfrag[kt], q[0], q[1]);
                mma_f16(acc2[2 * ntp + 1], hfrag[kt], q[2], q[3]);
            }
        }
        // ---- epilogue 2 item: bias + relu + l2norm + dot(UVEC) + store ----
        {
            const float* b2p = (const float*)(smem + OFF_B2) + 64;
            float ssA = 0.0f, ssB = 0.0f;
#pragma unroll
            for (int nt = 0; nt < 8; nt++) {
                int c0 = nt * 8 + tg * 2;
                acc2[nt][0] = fmaxf(acc2[nt][0] + b2p[c0],     0.0f);
                acc2[nt][1] = fmaxf(acc2[nt][1] + b2p[c0 + 1], 0.0f);
                acc2[nt][2] = fmaxf(acc2[nt][2] + b2p[c0],     0.0f);
                acc2[nt][3] = fmaxf(acc2[nt][3] + b2p[c0 + 1], 0.0f);
                ssA += acc2[nt][0] * acc2[nt][0] + acc2[nt][1] * acc2[nt][1];
                ssB += acc2[nt][2] * acc2[nt][2] + acc2[nt][3] * acc2[nt][3];
            }
            ssA += __shfl_xor_sync(0xffffffffu, ssA, 1);
            ssA += __shfl_xor_sync(0xffffffffu, ssA, 2);
            ssB += __shfl_xor_sync(0xffffffffu, ssB, 1);
            ssB += __shfl_xor_sync(0xffffffffu, ssB, 2);
            float invA = 1.0f / fmaxf(sqrtf(ssA), 1e-12f);
            float invB = 1.0f / fmaxf(sqrtf(ssB), 1e-12f);
            float dA = 0.0f, dB = 0.0f;
            uint32_t base = (uint32_t)((wid * 8) * 32 + lane) * 16u;
#pragma unroll
            for (int nt = 0; nt < 8; nt++) {
                float4 u = *(const float4*)(smem + OFF_UVEC + base + (uint32_t)nt * 512u);
                dA += u.x * acc2[nt][0] + u.y * acc2[nt][1];
                dB += u.z * acc2[nt][2] + u.w * acc2[nt][3];
            }
            dA *= invA;
            dB *= invB;
            dA += __shfl_xor_sync(0xffffffffu, dA, 1);
            dA += __shfl_xor_sync(0xffffffffu, dA, 2);
            dB += __shfl_xor_sync(0xffffffffu, dB, 1);
            dB += __shfl_xor_sync(0xffffffffu, dB, 2);
            if (tg == 0) {
                out[rowbase + rA] = dA;
                out[rowbase + rB] = dB;
            }
        }
        iid_hold = iid_next;
        __syncwarp();
    }
}

extern "C" void kernel_launch(void* const* d_in, const int* in_sizes, int n_in,
                              void* d_out, int out_size) {
    const int*   user_ids   = (const int*)d_in[0];
    const int*   item_ids   = (const int*)d_in[1];
    const float* user_table = (const float*)d_in[2];
    const float* item_table = (const float*)d_in[3];
    const float* uW1 = (const float*)d_in[4];
    const float* ub1 = (const float*)d_in[5];
    const float* uW2 = (const float*)d_in[6];
    const float* ub2 = (const float*)d_in[7];
    const float* iW1 = (const float*)d_in[8];
    const float* ib1 = (const float*)d_in[9];
    const float* iW2 = (const float*)d_in[10];
    const float* ib2 = (const float*)d_in[11];
    float* out = (float*)d_out;

    cudaFuncSetAttribute(twotower_kernel, cudaFuncAttributeMaxDynamicSharedMemorySize, SMEM_TOTAL);
    twotower_kernel<<<NCTAS, THREADS, SMEM_TOTAL>>>(
        user_ids, item_ids, user_table, item_table,
        uW1, ub1, uW2, ub2, iW1, ib1, iW2, ib2, out);
}

// round 11
// speedup vs baseline: 2.0592x; 1.2172x over previous
#include <cuda_runtime.h>
#include <cuda_fp16.h>
#include <cstdint>

// ============================================================================
// TwoTowerModel — independent-warp fp16 mma.sync, 32 rows/warp (weight LDS
// amortized over 2 rowblocks), register GEMM1->GEMM2 handoff, pipelined gather.
// (baseline sm_103 ISA: no tcgen05 — harness PTX target is sm_103)
// ============================================================================

static constexpr int BATCH   = 524288;
static constexpr int TILE    = 256;
static constexpr int NTILES  = BATCH / TILE;   // 2048
static constexpr int THREADS = 256;            // 8 warps x 32 rows = 256-row tile
static constexpr int NCTAS   = 148;

// ---- shared memory layout (bytes) ----
static constexpr int OFF_XFU  = 0;             // user emb fp16 [256][64] swizzled, 32K
static constexpr int OFF_XFI  = 32768;         // item emb fp16, 32K
static constexpr int OFF_UVEC = 65536;         // normalized user vec f32 frag-linear, 64K
static constexpr int OFF_W1F  = 131072;        // W1 frags: [tower]*16K = 32K
static constexpr int OFF_W2F  = 163840;        // W2 frags: 32K
static constexpr int OFF_B1   = 196608;        // float[2][128]
static constexpr int OFF_B2   = 197632;        // float[2][64]
static constexpr int SMEM_TOTAL = 198144;

__device__ __forceinline__ uint32_t smem_u32(const void* p) {
    uint32_t a;
    asm("{ .reg .u64 t; cvta.to.shared.u64 t, %1; cvt.u32.u64 %0, t; }" : "=r"(a) : "l"(p));
    return a;
}
__device__ __forceinline__ void mma_f16(float* d, const uint32_t* a, uint32_t b0, uint32_t b1) {
    asm volatile("mma.sync.aligned.m16n8k16.row.col.f32.f16.f16.f32 "
        "{%0,%1,%2,%3}, {%4,%5,%6,%7}, {%8,%9}, {%0,%1,%2,%3};"
        : "+f"(d[0]), "+f"(d[1]), "+f"(d[2]), "+f"(d[3])
        : "r"(a[0]), "r"(a[1]), "r"(a[2]), "r"(a[3]), "r"(b0), "r"(b1));
}
__device__ __forceinline__ void ldm4(uint32_t* a, uint32_t addr) {
    asm volatile("ldmatrix.sync.aligned.m8n8.x4.shared.b16 {%0,%1,%2,%3}, [%4];"
        : "=r"(a[0]), "=r"(a[1]), "=r"(a[2]), "=r"(a[3]) : "r"(addr) : "memory");
}
__device__ __forceinline__ void lds128(uint32_t* q, uint32_t addr) {
    asm volatile("ld.shared.v4.b32 {%0,%1,%2,%3}, [%4];"
        : "=r"(q[0]), "=r"(q[1]), "=r"(q[2]), "=r"(q[3]) : "r"(addr));
}
__device__ __forceinline__ uint32_t packh2(float a, float b) {
    __half2 h = __floats2half2_rn(a, b);
    return *(uint32_t*)&h;
}

__global__ __launch_bounds__(THREADS, 1)
void twotower_kernel(
    const int* __restrict__ user_ids, const int* __restrict__ item_ids,
    const float* __restrict__ user_table, const float* __restrict__ item_table,
    const float* __restrict__ uW1, const float* __restrict__ ub1,
    const float* __restrict__ uW2, const float* __restrict__ ub2,
    const float* __restrict__ iW1, const float* __restrict__ ib1,
    const float* __restrict__ iW2, const float* __restrict__ ib2,
    float* __restrict__ out)
{
    extern __shared__ char smem[];
    const uint32_t sb = smem_u32(smem);
    const int tid  = threadIdx.x;
    const int wid  = tid >> 5;
    const int lane = tid & 31;
    const int tg   = lane & 3;
    const int g    = lane >> 2;
    const int khalf = lane >> 4;

    // ============ stage weights as nt-paired mma B-fragments (fp16) ====
    for (int t = 0; t < 2; t++) {
        const float* gW1 = t ? iW1 : uW1;   // [64][128] row-major
        const float* gW2 = t ? iW2 : uW2;   // [128][64]
        const float* gb1 = t ? ib1 : ub1;
        const float* gb2 = t ? ib2 : ub2;
        for (int p = tid; p < 1024; p += THREADS) {       // W1: kt(4) x ntp(8) x lane(32)
            int kt = p >> 8, ntp = (p >> 5) & 7, ln = p & 31;
            int ltg = ln & 3, lg = ln >> 2;
            int k0 = kt * 16 + ltg * 2;
            uint32_t q[4];
#pragma unroll
            for (int s = 0; s < 2; s++) {
                int n = (2 * ntp + s) * 8 + lg;
                q[2 * s + 0] = packh2(__ldg(gW1 + k0 * 128 + n),       __ldg(gW1 + (k0 + 1) * 128 + n));
                q[2 * s + 1] = packh2(__ldg(gW1 + (k0 + 8) * 128 + n), __ldg(gW1 + (k0 + 9) * 128 + n));
            }
            *((uint4*)(smem + OFF_W1F + t * 16384) + p) = make_uint4(q[0], q[1], q[2], q[3]);
        }
        for (int p = tid; p < 1024; p += THREADS) {       // W2: kt(8) x ntp(4) x lane(32)
            int kt = p >> 7, ntp = (p >> 5) & 3, ln = p & 31;
            int ltg = ln & 3, lg = ln >> 2;
            int k0 = kt * 16 + ltg * 2;
            uint32_t q[4];
#pragma unroll
            for (int s = 0; s < 2; s++) {
                int n = (2 * ntp + s) * 8 + lg;
                q[2 * s + 0] = packh2(__ldg(gW2 + k0 * 64 + n),       __ldg(gW2 + (k0 + 1) * 64 + n));
                q[2 * s + 1] = packh2(__ldg(gW2 + (k0 + 8) * 64 + n), __ldg(gW2 + (k0 + 9) * 64 + n));
            }
            *((uint4*)(smem + OFF_W2F + t * 16384) + p) = make_uint4(q[0], q[1], q[2], q[3]);
        }
        if (tid < 128) ((float*)(smem + OFF_B1))[t * 128 + tid] = __ldg(gb1 + tid);
        if (tid < 64)  ((float*)(smem + OFF_B2))[t * 64 + tid]  = __ldg(gb2 + tid);
    }
    __syncthreads();

    const int wrow0 = wid * 32;               // warp's 32-row slab base
    const int myrow = wrow0 + lane;           // gather row (1 row/lane)
    const uint32_t mr7 = (uint32_t)(myrow & 7);
    const int lr0 = wrow0 + (lane & 15);      // ldmatrix source rows
    const int lr1 = lr0 + 16;
    const uint32_t l0b = (uint32_t)lr0 * 128, l1b = (uint32_t)lr1 * 128;
    const uint32_t l0x = (uint32_t)(lr0 & 7), l1x = (uint32_t)(lr1 & 7);

    // ---------------- prologue: stage tile0 user rows + item id ----------------
    int tile = blockIdx.x;
    float4 stg[16];
    {
        int uid = __ldg(user_ids + tile * TILE + myrow);
        const float4* src = (const float4*)(user_table + (size_t)uid * 64);
#pragma unroll
        for (int j = 0; j < 16; j++) stg[j] = __ldg(src + j);
    }
    int iid_hold = __ldg(item_ids + tile * TILE + myrow);

    for (; tile < NTILES; tile += gridDim.x) {
        const int rowbase = tile * TILE;
        int tnext = tile + (int)gridDim.x;
        if (tnext >= NTILES) tnext = tile;    // harmless reload on last iteration

        // ---- 1. convert staged user rows -> XFU (fp16, swizzled) ----
#pragma unroll
        for (int j = 0; j < 8; j++) {
            float4 a = stg[2 * j], b = stg[2 * j + 1];
            uint4 o = make_uint4(packh2(a.x, a.y), packh2(a.z, a.w),
                                 packh2(b.x, b.y), packh2(b.z, b.w));
            *(uint4*)(smem + OFF_XFU + (uint32_t)myrow * 128 + (((uint32_t)j ^ mr7) << 4)) = o;
        }
        __syncwarp();

        // ---- 2. issue item gather (staging regs now free) ----
        {
            const float4* src = (const float4*)(item_table + (size_t)iid_hold * 64);
#pragma unroll
            for (int j = 0; j < 16; j++) stg[j] = __ldg(src + j);
        }
        // ---- 3. prefetch next-tile ids ----
        int uid_next = __ldg(user_ids + tnext * TILE + myrow);
        int iid_next = __ldg(item_ids + tnext * TILE + myrow);

        uint32_t hfrag[2][8][4];
        float acc2[2][8][4];

        // ================= USER tower =================
        // ---- GEMM1: 2 nt-halves x (4 kt x 4 ntp), weights shared by 2 rowblocks ----
#pragma unroll
        for (int h = 0; h < 2; h++) {
            float acc1[2][8][4];
#pragma unroll
            for (int rb = 0; rb < 2; rb++)
#pragma unroll
                for (int i = 0; i < 8; i++)
#pragma unroll
                    for (int j = 0; j < 4; j++) acc1[rb][i][j] = 0.0f;
#pragma unroll
            for (int kt = 0; kt < 4; kt++) {
                uint32_t A0[4], A1[4];
                uint32_t chg = (uint32_t)(kt * 2 + khalf);
                ldm4(A0, sb + OFF_XFU + l0b + ((chg ^ l0x) << 4));
                ldm4(A1, sb + OFF_XFU + l1b + ((chg ^ l1x) << 4));
                uint32_t wb = sb + OFF_W1F + ((uint32_t)((kt * 8 + h * 4) * 32 + lane)) * 16;
#pragma unroll
                for (int i = 0; i < 4; i++) {
                    uint32_t q[4];
                    lds128(q, wb + (uint32_t)i * 512);
                    mma_f16(acc1[0][2 * i],     A0, q[0], q[1]);
                    mma_f16(acc1[0][2 * i + 1], A0, q[2], q[3]);
                    mma_f16(acc1[1][2 * i],     A1, q[0], q[1]);
                    mma_f16(acc1[1][2 * i + 1], A1, q[2], q[3]);
                }
            }
            // ep1: bias+relu -> hfrag[rb][4h+kp] (GEMM2 A-frags, in-register)
            const float* b1p = (const float*)(smem + OFF_B1);
#pragma unroll
            for (int rb = 0; rb < 2; rb++)
#pragma unroll
                for (int kp = 0; kp < 4; kp++) {
                    int lA = 2 * kp, lB = 2 * kp + 1;
                    int cA = (8 * h + lA) * 8 + tg * 2, cB = (8 * h + lB) * 8 + tg * 2;
                    hfrag[rb][4 * h + kp][0] = packh2(fmaxf(acc1[rb][lA][0] + b1p[cA],     0.0f),
                                                     fmaxf(acc1[rb][lA][1] + b1p[cA + 1], 0.0f));
                    hfrag[rb][4 * h + kp][1] = packh2(fmaxf(acc1[rb][lA][2] + b1p[cA],     0.0f),
                                                     fmaxf(acc1[rb][lA][3] + b1p[cA + 1], 0.0f));
                    hfrag[rb][4 * h + kp][2] = packh2(fmaxf(acc1[rb][lB][0] + b1p[cB],     0.0f),
                                                     fmaxf(acc1[rb][lB][1] + b1p[cB + 1], 0.0f));
                    hfrag[rb][4 * h + kp][3] = packh2(fmaxf(acc1[rb][lB][2] + b1p[cB],     0.0f),
                                                     fmaxf(acc1[rb][lB][3] + b1p[cB + 1], 0.0f));
                }
        }
        // ---- GEMM2 user ----
#pragma unroll
        for (int rb = 0; rb < 2; rb++)
#pragma unroll
            for (int i = 0; i < 8; i++)
#pragma unroll
                for (int j = 0; j < 4; j++) acc2[rb][i][j] = 0.0f;
#pragma unroll
        for (int kt = 0; kt < 8; kt++) {
            uint32_t wb = sb + OFF_W2F + ((uint32_t)(kt * 4 * 32 + lane)) * 16;
#pragma unroll
            for (int ntp = 0; ntp < 4; ntp++) {
                uint32_t q[4];
                lds128(q, wb + (uint32_t)ntp * 512);
                mma_f16(acc2[0][2 * ntp],     hfrag[0][kt], q[0], q[1]);
                mma_f16(acc2[0][2 * ntp + 1], hfrag[0][kt], q[2], q[3]);
                mma_f16(acc2[1][2 * ntp],     hfrag[1][kt], q[0], q[1]);
                mma_f16(acc2[1][2 * ntp + 1], hfrag[1][kt], q[2], q[3]);
            }
        }
        // ---- ep2 user: bias + relu + l2norm -> UVEC (f32 frag-linear) ----
        {
            const float* b2p = (const float*)(smem + OFF_B2);
#pragma unroll
            for (int rb = 0; rb < 2; rb++) {
                float ssA = 0.0f, ssB = 0.0f;
#pragma unroll
                for (int nt = 0; nt < 8; nt++) {
                    int c0 = nt * 8 + tg * 2;
                    acc2[rb][nt][0] = fmaxf(acc2[rb][nt][0] + b2p[c0],     0.0f);
                    acc2[rb][nt][1] = fmaxf(acc2[rb][nt][1] + b2p[c0 + 1], 0.0f);
                    acc2[rb][nt][2] = fmaxf(acc2[rb][nt][2] + b2p[c0],     0.0f);
                    acc2[rb][nt][3] = fmaxf(acc2[rb][nt][3] + b2p[c0 + 1], 0.0f);
                    ssA += acc2[rb][nt][0] * acc2[rb][nt][0] + acc2[rb][nt][1] * acc2[rb][nt][1];
                    ssB += acc2[rb][nt][2] * acc2[rb][nt][2] + acc2[rb][nt][3] * acc2[rb][nt][3];
                }
                ssA += __shfl_xor_sync(0xffffffffu, ssA, 1);
                ssA += __shfl_xor_sync(0xffffffffu, ssA, 2);
                ssB += __shfl_xor_sync(0xffffffffu, ssB, 1);
                ssB += __shfl_xor_sync(0xffffffffu, ssB, 2);
                float invA = 1.0f / fmaxf(sqrtf(ssA), 1e-12f);
                float invB = 1.0f / fmaxf(sqrtf(ssB), 1e-12f);
                uint32_t base = (uint32_t)(((wid * 2 + rb) * 8) * 32 + lane) * 16u;
#pragma unroll
                for (int nt = 0; nt < 8; nt++) {
                    float4 v = make_float4(acc2[rb][nt][0] * invA, acc2[rb][nt][1] * invA,
                                           acc2[rb][nt][2] * invB, acc2[rb][nt][3] * invB);
                    *(float4*)(smem + OFF_UVEC + base + (uint32_t)nt * 512u) = v;
                }
            }
        }
        __syncwarp();

        // ---- 5. convert item rows -> XFI; staging freed ----
#pragma unroll
        for (int j = 0; j < 8; j++) {
            float4 a = stg[2 * j], b = stg[2 * j + 1];
            uint4 o = make_uint4(packh2(a.x, a.y), packh2(a.z, a.w),
                                 packh2(b.x, b.y), packh2(b.z, b.w));
            *(uint4*)(smem + OFF_XFI + (uint32_t)myrow * 128 + (((uint32_t)j ^ mr7) << 4)) = o;
        }
        __syncwarp();

        // ---- 6. issue next-tile user gather into staging ----
        {
            const float4* src = (const float4*)(user_table + (size_t)uid_next * 64);
#pragma unroll
            for (int j = 0; j < 16; j++) stg[j] = __ldg(src + j);
        }

        // ================= ITEM tower =================
#pragma unroll
        for (int h = 0; h < 2; h++) {
            float acc1[2][8][4];
#pragma unroll
            for (int rb = 0; rb < 2; rb++)
#pragma unroll
                for (int i = 0; i < 8; i++)
#pragma unroll
                    for (int j = 0; j < 4; j++) acc1[rb][i][j] = 0.0f;
#pragma unroll
            for (int kt = 0; kt < 4; kt++) {
                uint32_t A0[4], A1[4];
                uint32_t chg = (uint32_t)(kt * 2 + khalf);
                ldm4(A0, sb + OFF_XFI + l0b + ((chg ^ l0x) << 4));
                ldm4(A1, sb + OFF_XFI + l1b + ((chg ^ l1x) << 4));
                uint32_t wb = sb + OFF_W1F + 16384u + ((uint32_t)((kt * 8 + h * 4) * 32 + lane)) * 16;
#pragma unroll
                for (int i = 0; i < 4; i++) {
                    uint32_t q[4];
                    lds128(q, wb + (uint32_t)i * 512);
                    mma_f16(acc1[0][2 * i],     A0, q[0], q[1]);
                    mma_f16(acc1[0][2 * i + 1], A0, q[2], q[3]);
                    mma_f16(acc1[1][2 * i],     A1, q[0], q[1]);
                    mma_f16(acc1[1][2 * i + 1], A1, q[2], q[3]);
                }
            }
            const float* b1p = (const float*)(smem + OFF_B1) + 128;
#pragma unroll
            for (int rb = 0; rb < 2; rb++)
#pragma unroll
                for (int kp = 0; kp < 4; kp++) {
                    int lA = 2 * kp, lB = 2 * kp + 1;
                    int cA = (8 * h + lA) * 8 + tg * 2, cB = (8 * h + lB) * 8 + tg * 2;
                    hfrag[rb][4 * h + kp][0] = packh2(fmaxf(acc1[rb][lA][0] + b1p[cA],     0.0f),
                                                     fmaxf(acc1[rb][lA][1] + b1p[cA + 1], 0.0f));
                    hfrag[rb][4 * h + kp][1] = packh2(fmaxf(acc1[rb][lA][2] + b1p[cA],     0.0f),
                                                     fmaxf(acc1[rb][lA][3] + b1p[cA + 1], 0.0f));
                    hfrag[rb][4 * h + kp][2] = packh2(fmaxf(acc1[rb][lB][0] + b1p[cB],     0.0f),
                                                     fmaxf(acc1[rb][lB][1] + b1p[cB + 1], 0.0f));
                    hfrag[rb][4 * h + kp][3] = packh2(fmaxf(acc1[rb][lB][2] + b1p[cB],     0.0f),
                                                     fmaxf(acc1[rb][lB][3] + b1p[cB + 1], 0.0f));
                }
        }
        // ---- GEMM2 item ----
#pragma unroll
        for (int rb = 0; rb < 2; rb++)
#pragma unroll
            for (int i = 0; i < 8; i++)
#pragma unroll
                for (int j = 0; j < 4; j++) acc2[rb][i][j] = 0.0f;
#pragma unroll
        for (int kt = 0; kt < 8; kt++) {
            uint32_t wb = sb + OFF_W2F + 16384u + ((uint32_t)(kt * 4 * 32 + lane)) * 16;
#pragma unroll
            for (int ntp = 0; ntp < 4; ntp++) {
                uint32_t q[4];
                lds128(q, wb + (uint32_t)ntp * 512);
                mma_f16(acc2[0][2 * ntp],     hfrag[0][kt], q[0], q[1]);
                mma_f16(acc2[0][2 * ntp + 1], hfrag[0][kt], q[2], q[3]);
                mma_f16(acc2[1][2 * ntp],     hfrag[1][kt], q[0], q[1]);
                mma_f16(acc2[1][2 * ntp + 1], hfrag[1][kt], q[2], q[3]);
            }
        }
        // ---- ep2 item: bias + relu + l2norm + dot(UVEC) + store ----
        {
            const float* b2p = (const float*)(smem + OFF_B2) + 64;
#pragma unroll
            for (int rb = 0; rb < 2; rb++) {
                float ssA = 0.0f, ssB = 0.0f;
#pragma unroll
                for (int nt = 0; nt < 8; nt++) {
                    int c0 = nt * 8 + tg * 2;
                    acc2[rb][nt][0] = fmaxf(acc2[rb][nt][0] + b2p[c0],     0.0f);
                    acc2[rb][nt][1] = fmaxf(acc2[rb][nt][1] + b2p[c0 + 1], 0.0f);
                    acc2[rb][nt][2] = fmaxf(acc2[rb][nt][2] + b2p[c0],     0.0f);
                    acc2[rb][nt][3] = fmaxf(acc2[rb][nt][3] + b2p[c0 + 1], 0.0f);
                    ssA += acc2[rb][nt][0] * acc2[rb][nt][0] + acc2[rb][nt][1] * acc2[rb][nt][1];
                    ssB += acc2[rb][nt][2] * acc2[rb][nt][2] + acc2[rb][nt][3] * acc2[rb][nt][3];
                }
                ssA += __shfl_xor_sync(0xffffffffu, ssA, 1);
                ssA += __shfl_xor_sync(0xffffffffu, ssA, 2);
                ssB += __shfl_xor_sync(0xffffffffu, ssB, 1);
                ssB += __shfl_xor_sync(0xffffffffu, ssB, 2);
                float invA = 1.0f / fmaxf(sqrtf(ssA), 1e-12f);
                float invB = 1.0f / fmaxf(sqrtf(ssB), 1e-12f);
                float dA = 0.0f, dB = 0.0f;
                uint32_t base = (uint32_t)(((wid * 2 + rb) * 8) * 32 + lane) * 16u;
#pragma unroll
                for (int nt = 0; nt < 8; nt++) {
                    float4 u = *(const float4*)(smem + OFF_UVEC + base + (uint32_t)nt * 512u);
                    dA += u.x * acc2[rb][nt][0] + u.y * acc2[rb][nt][1];
                    dB += u.z * acc2[rb][nt][2] + u.w * acc2[rb][nt][3];
                }
                dA *= invA;
                dB *= invB;
                dA += __shfl_xor_sync(0xffffffffu, dA, 1);
                dA += __shfl_xor_sync(0xffffffffu, dA, 2);
                dB += __shfl_xor_sync(0xffffffffu, dB, 1);
                dB += __shfl_xor_sync(0xffffffffu, dB, 2);
                if (tg == 0) {
                    int r = rowbase + wrow0 + rb * 16 + g;
                    out[r]     = dA;
                    out[r + 8] = dB;
                }
            }
        }
        iid_hold = iid_next;
        __syncwarp();
    }
}

extern "C" void kernel_launch(void* const* d_in, const int* in_sizes, int n_in,
                              void* d_out, int out_size) {
    const int*   user_ids   = (const int*)d_in[0];
    const int*   item_ids   = (const int*)d_in[1];
    const float* user_table = (const float*)d_in[2];
    const float* item_table = (const float*)d_in[3];
    const float* uW1 = (const float*)d_in[4];
    const float* ub1 = (const float*)d_in[5];
    const float* uW2 = (const float*)d_in[6];
    const float* ub2 = (const float*)d_in[7];
    const float* iW1 = (const float*)d_in[8];
    const float* ib1 = (const float*)d_in[9];
    const float* iW2 = (const float*)d_in[10];
    const float* ib2 = (const float*)d_in[11];
    float* out = (float*)d_out;

    cudaFuncSetAttribute(twotower_kernel, cudaFuncAttributeMaxDynamicSharedMemorySize, SMEM_TOTAL);
    twotower_kernel<<<NCTAS, THREADS, SMEM_TOTAL>>>(
        user_ids, item_ids, user_table, item_table,
        uW1, ub1, uW2, ub2, iW1, ib1, iW2, ib2, out);
}

// round 12
// speedup vs baseline: 2.4343x; 1.1821x over previous
#include <cuda_runtime.h>
#include <cuda_fp16.h>
#include <cstdint>

// ============================================================================
// TwoTowerModel — independent-warp fp16 mma.sync, 32 rows/warp, register
// GEMM1->GEMM2 handoff, line-coalesced gather (8 lanes/row), fp16 UVEC.
// (baseline sm_103 ISA: no tcgen05 — harness PTX target is sm_103)
// ============================================================================

static constexpr int BATCH   = 524288;
static constexpr int TILE    = 256;
static constexpr int NTILES  = BATCH / TILE;   // 2048
static constexpr int THREADS = 256;            // 8 warps x 32 rows = 256-row tile
static constexpr int NCTAS   = 148;

// ---- shared memory layout (bytes) ----
static constexpr int OFF_XFU  = 0;             // user emb fp16 [256][64] swizzled, 32K
static constexpr int OFF_XFI  = 32768;         // item emb fp16, 32K
static constexpr int OFF_UVEC = 65536;         // normalized user vec fp16 frag-linear, 32K
static constexpr int OFF_W1F  = 98304;         // W1 frags: [tower]*16K = 32K
static constexpr int OFF_W2F  = 131072;        // W2 frags: 32K
static constexpr int OFF_B1   = 163840;        // float[2][128]
static constexpr int OFF_B2   = 164864;        // float[2][64]
static constexpr int SMEM_TOTAL = 165376;

__device__ __forceinline__ uint32_t smem_u32(const void* p) {
    uint32_t a;
    asm("{ .reg .u64 t; cvta.to.shared.u64 t, %1; cvt.u32.u64 %0, t; }" : "=r"(a) : "l"(p));
    return a;
}
__device__ __forceinline__ void mma_f16(float* d, const uint32_t* a, uint32_t b0, uint32_t b1) {
    asm volatile("mma.sync.aligned.m16n8k16.row.col.f32.f16.f16.f32 "
        "{%0,%1,%2,%3}, {%4,%5,%6,%7}, {%8,%9}, {%0,%1,%2,%3};"
        : "+f"(d[0]), "+f"(d[1]), "+f"(d[2]), "+f"(d[3])
        : "r"(a[0]), "r"(a[1]), "r"(a[2]), "r"(a[3]), "r"(b0), "r"(b1));
}
__device__ __forceinline__ void ldm4(uint32_t* a, uint32_t addr) {
    asm volatile("ldmatrix.sync.aligned.m8n8.x4.shared.b16 {%0,%1,%2,%3}, [%4];"
        : "=r"(a[0]), "=r"(a[1]), "=r"(a[2]), "=r"(a[3]) : "r"(addr) : "memory");
}
__device__ __forceinline__ void lds128(uint32_t* q, uint32_t addr) {
    asm volatile("ld.shared.v4.b32 {%0,%1,%2,%3}, [%4];"
        : "=r"(q[0]), "=r"(q[1]), "=r"(q[2]), "=r"(q[3]) : "r"(addr));
}
__device__ __forceinline__ uint32_t packh2(float a, float b) {
    __half2 h = __floats2half2_rn(a, b);
    return *(uint32_t*)&h;
}

__global__ __launch_bounds__(THREADS, 1)
void twotower_kernel(
    const int* __restrict__ user_ids, const int* __restrict__ item_ids,
    const float* __restrict__ user_table, const float* __restrict__ item_table,
    const float* __restrict__ uW1, const float* __restrict__ ub1,
    const float* __restrict__ uW2, const float* __restrict__ ub2,
    const float* __restrict__ iW1, const float* __restrict__ ib1,
    const float* __restrict__ iW2, const float* __restrict__ ib2,
    float* __restrict__ out)
{
    extern __shared__ char smem[];
    const uint32_t sb = smem_u32(smem);
    const int tid  = threadIdx.x;
    const int wid  = tid >> 5;
    const int lane = tid & 31;
    const int tg   = lane & 3;
    const int g    = lane >> 2;
    const int khalf = lane >> 4;

    // ============ stage weights as nt-paired mma B-fragments (fp16) ====
    for (int t = 0; t < 2; t++) {
        const float* gW1 = t ? iW1 : uW1;   // [64][128] row-major
        const float* gW2 = t ? iW2 : uW2;   // [128][64]
        const float* gb1 = t ? ib1 : ub1;
        const float* gb2 = t ? ib2 : ub2;
        for (int p = tid; p < 1024; p += THREADS) {       // W1: kt(4) x ntp(8) x lane(32)
            int kt = p >> 8, ntp = (p >> 5) & 7, ln = p & 31;
            int ltg = ln & 3, lg = ln >> 2;
            int k0 = kt * 16 + ltg * 2;
            uint32_t q[4];
#pragma unroll
            for (int s = 0; s < 2; s++) {
                int n = (2 * ntp + s) * 8 + lg;
                q[2 * s + 0] = packh2(__ldg(gW1 + k0 * 128 + n),       __ldg(gW1 + (k0 + 1) * 128 + n));
                q[2 * s + 1] = packh2(__ldg(gW1 + (k0 + 8) * 128 + n), __ldg(gW1 + (k0 + 9) * 128 + n));
            }
            *((uint4*)(smem + OFF_W1F + t * 16384) + p) = make_uint4(q[0], q[1], q[2], q[3]);
        }
        for (int p = tid; p < 1024; p += THREADS) {       // W2: kt(8) x ntp(4) x lane(32)
            int kt = p >> 7, ntp = (p >> 5) & 3, ln = p & 31;
            int ltg = ln & 3, lg = ln >> 2;
            int k0 = kt * 16 + ltg * 2;
            uint32_t q[4];
#pragma unroll
            for (int s = 0; s < 2; s++) {
                int n = (2 * ntp + s) * 8 + lg;
                q[2 * s + 0] = packh2(__ldg(gW2 + k0 * 64 + n),       __ldg(gW2 + (k0 + 1) * 64 + n));
                q[2 * s + 1] = packh2(__ldg(gW2 + (k0 + 8) * 64 + n), __ldg(gW2 + (k0 + 9) * 64 + n));
            }
            *((uint4*)(smem + OFF_W2F + t * 16384) + p) = make_uint4(q[0], q[1], q[2], q[3]);
        }
        if (tid < 128) ((float*)(smem + OFF_B1))[t * 128 + tid] = __ldg(gb1 + tid);
        if (tid < 64)  ((float*)(smem + OFF_B2))[t * 64 + tid]  = __ldg(gb2 + tid);
    }
    __syncthreads();

    const int wrow0 = wid * 32;               // warp's 32-row slab base
    const int myrow = wrow0 + lane;           // id-resident row (1 id/lane)
    // coalesced-gather decomposition: 8 lanes per row, 4 rows per instruction
    const int rg = lane >> 3;                 // row-in-group-of-4
    const int gs = lane & 7;                  // 16B sector within 128B line
    const int lr0 = wrow0 + (lane & 15);      // ldmatrix source rows
    const int lr1 = lr0 + 16;
    const uint32_t l0b = (uint32_t)lr0 * 128, l1b = (uint32_t)lr1 * 128;
    const uint32_t l0x = (uint32_t)(lr0 & 7), l1x = (uint32_t)(lr1 & 7);

    // ---------------- prologue: stage tile0 user rows + item id ----------------
    int tile = blockIdx.x;
    float4 stg[16];
    {
        int uid = __ldg(user_ids + tile * TILE + myrow);
#pragma unroll
        for (int k = 0; k < 8; k++) {
            int idk = __shfl_sync(0xffffffffu, uid, k * 4 + rg);
            const float4* src = (const float4*)(user_table + (size_t)(uint32_t)idk * 64);
            stg[k]     = __ldg(src + gs);
            stg[k + 8] = __ldg(src + 8 + gs);
        }
    }
    int iid_hold = __ldg(item_ids + tile * TILE + myrow);

    for (; tile < NTILES; tile += gridDim.x) {
        const int rowbase = tile * TILE;
        int tnext = tile + (int)gridDim.x;
        if (tnext >= NTILES) tnext = tile;    // harmless reload on last iteration

        // ---- 1. convert staged user rows -> XFU (fp16, swizzled, 8B pieces) ----
#pragma unroll
        for (int j = 0; j < 16; j++) {
            int k = j & 7, half = j >> 3;
            int r = wrow0 + k * 4 + rg;
            float4 v = stg[half * 8 + k];
            uint32_t chunk = (uint32_t)(half * 4 + (gs >> 1));
            uint32_t ad = (uint32_t)r * 128 + ((chunk ^ (uint32_t)(r & 7)) << 4) + (uint32_t)(gs & 1) * 8;
            *(uint2*)(smem + OFF_XFU + ad) = make_uint2(packh2(v.x, v.y), packh2(v.z, v.w));
        }
        __syncwarp();

        // ---- 2. issue item gather (coalesced, staging regs now free) ----
#pragma unroll
        for (int k = 0; k < 8; k++) {
            int idk = __shfl_sync(0xffffffffu, iid_hold, k * 4 + rg);
            const float4* src = (const float4*)(item_table + (size_t)(uint32_t)idk * 64);
            stg[k]     = __ldg(src + gs);
            stg[k + 8] = __ldg(src + 8 + gs);
        }
        // ---- 3. prefetch next-tile ids ----
        int uid_next = __ldg(user_ids + tnext * TILE + myrow);
        int iid_next = __ldg(item_ids + tnext * TILE + myrow);

        uint32_t hfrag[2][8][4];
        float acc2[2][8][4];

        // ================= USER tower =================
        // ---- GEMM1: 2 nt-halves x (4 kt x 4 ntp), weights shared by 2 rowblocks ----
#pragma unroll
        for (int h = 0; h < 2; h++) {
            float acc1[2][8][4];
#pragma unroll
            for (int rb = 0; rb < 2; rb++)
#pragma unroll
                for (int i = 0; i < 8; i++)
#pragma unroll
                    for (int j = 0; j < 4; j++) acc1[rb][i][j] = 0.0f;
#pragma unroll
            for (int kt = 0; kt < 4; kt++) {
                uint32_t A0[4], A1[4];
                uint32_t chg = (uint32_t)(kt * 2 + khalf);
                ldm4(A0, sb + OFF_XFU + l0b + ((chg ^ l0x) << 4));
                ldm4(A1, sb + OFF_XFU + l1b + ((chg ^ l1x) << 4));
                uint32_t wb = sb + OFF_W1F + ((uint32_t)((kt * 8 + h * 4) * 32 + lane)) * 16;
#pragma unroll
                for (int i = 0; i < 4; i++) {
                    uint32_t q[4];
                    lds128(q, wb + (uint32_t)i * 512);
                    mma_f16(acc1[0][2 * i],     A0, q[0], q[1]);
                    mma_f16(acc1[0][2 * i + 1], A0, q[2], q[3]);
                    mma_f16(acc1[1][2 * i],     A1, q[0], q[1]);
                    mma_f16(acc1[1][2 * i + 1], A1, q[2], q[3]);
                }
            }
            // ep1: bias+relu -> hfrag[rb][4h+kp] (GEMM2 A-frags, in-register)
            const float* b1p = (const float*)(smem + OFF_B1);
#pragma unroll
            for (int rb = 0; rb < 2; rb++)
#pragma unroll
                for (int kp = 0; kp < 4; kp++) {
                    int lA = 2 * kp, lB = 2 * kp + 1;
                    int cA = (8 * h + lA) * 8 + tg * 2, cB = (8 * h + lB) * 8 + tg * 2;
                    hfrag[rb][4 * h + kp][0] = packh2(fmaxf(acc1[rb][lA][0] + b1p[cA],     0.0f),
                                                     fmaxf(acc1[rb][lA][1] + b1p[cA + 1], 0.0f));
                    hfrag[rb][4 * h + kp][1] = packh2(fmaxf(acc1[rb][lA][2] + b1p[cA],     0.0f),
                                                     fmaxf(acc1[rb][lA][3] + b1p[cA + 1], 0.0f));
                    hfrag[rb][4 * h + kp][2] = packh2(fmaxf(acc1[rb][lB][0] + b1p[cB],     0.0f),
                                                     fmaxf(acc1[rb][lB][1] + b1p[cB + 1], 0.0f));
                    hfrag[rb][4 * h + kp][3] = packh2(fmaxf(acc1[rb][lB][2] + b1p[cB],     0.0f),
                                                     fmaxf(acc1[rb][lB][3] + b1p[cB + 1], 0.0f));
                }
        }
        // ---- GEMM2 user ----
#pragma unroll
        for (int rb = 0; rb < 2; rb++)
#pragma unroll
            for (int i = 0; i < 8; i++)
#pragma unroll
                for (int j = 0; j < 4; j++) acc2[rb][i][j] = 0.0f;
#pragma unroll
        for (int kt = 0; kt < 8; kt++) {
            uint32_t wb = sb + OFF_W2F + ((uint32_t)(kt * 4 * 32 + lane)) * 16;
#pragma unroll
            for (int ntp = 0; ntp < 4; ntp++) {
                uint32_t q[4];
                lds128(q, wb + (uint32_t)ntp * 512);
                mma_f16(acc2[0][2 * ntp],     hfrag[0][kt], q[0], q[1]);
                mma_f16(acc2[0][2 * ntp + 1], hfrag[0][kt], q[2], q[3]);
                mma_f16(acc2[1][2 * ntp],     hfrag[1][kt], q[0], q[1]);
                mma_f16(acc2[1][2 * ntp + 1], hfrag[1][kt], q[2], q[3]);
            }
        }
        // ---- ep2 user: bias + relu + l2norm -> UVEC (fp16 frag-linear) ----
        {
            const float* b2p = (const float*)(smem + OFF_B2);
#pragma unroll
            for (int rb = 0; rb < 2; rb++) {
                float ssA = 0.0f, ssB = 0.0f;
#pragma unroll
                for (int nt = 0; nt < 8; nt++) {
                    int c0 = nt * 8 + tg * 2;
                    acc2[rb][nt][0] = fmaxf(acc2[rb][nt][0] + b2p[c0],     0.0f);
                    acc2[rb][nt][1] = fmaxf(acc2[rb][nt][1] + b2p[c0 + 1], 0.0f);
                    acc2[rb][nt][2] = fmaxf(acc2[rb][nt][2] + b2p[c0],     0.0f);
                    acc2[rb][nt][3] = fmaxf(acc2[rb][nt][3] + b2p[c0 + 1], 0.0f);
                    ssA += acc2[rb][nt][0] * acc2[rb][nt][0] + acc2[rb][nt][1] * acc2[rb][nt][1];
                    ssB += acc2[rb][nt][2] * acc2[rb][nt][2] + acc2[rb][nt][3] * acc2[rb][nt][3];
                }
                ssA += __shfl_xor_sync(0xffffffffu, ssA, 1);
                ssA += __shfl_xor_sync(0xffffffffu, ssA, 2);
                ssB += __shfl_xor_sync(0xffffffffu, ssB, 1);
                ssB += __shfl_xor_sync(0xffffffffu, ssB, 2);
                float invA = 1.0f / fmaxf(sqrtf(ssA), 1e-12f);
                float invB = 1.0f / fmaxf(sqrtf(ssB), 1e-12f);
                uint32_t base = (uint32_t)(((wid * 2 + rb) * 8) * 32 + lane) * 8u;
#pragma unroll
                for (int nt = 0; nt < 8; nt++) {
                    uint2 v = make_uint2(packh2(acc2[rb][nt][0] * invA, acc2[rb][nt][1] * invA),
                                         packh2(acc2[rb][nt][2] * invB, acc2[rb][nt][3] * invB));
                    *(uint2*)(smem + OFF_UVEC + base + (uint32_t)nt * 256u) = v;
                }
            }
        }
        __syncwarp();

        // ---- 5. convert item rows -> XFI; staging freed ----
#pragma unroll
        for (int j = 0; j < 16; j++) {
            int k = j & 7, half = j >> 3;
            int r = wrow0 + k * 4 + rg;
            float4 v = stg[half * 8 + k];
            uint32_t chunk = (uint32_t)(half * 4 + (gs >> 1));
            uint32_t ad = (uint32_t)r * 128 + ((chunk ^ (uint32_t)(r & 7)) << 4) + (uint32_t)(gs & 1) * 8;
            *(uint2*)(smem + OFF_XFI + ad) = make_uint2(packh2(v.x, v.y), packh2(v.z, v.w));
        }
        __syncwarp();

        // ---- 6. issue next-tile user gather into staging ----
#pragma unroll
        for (int k = 0; k < 8; k++) {
            int idk = __shfl_sync(0xffffffffu, uid_next, k * 4 + rg);
            const float4* src = (const float4*)(user_table + (size_t)(uint32_t)idk * 64);
            stg[k]     = __ldg(src + gs);
            stg[k + 8] = __ldg(src + 8 + gs);
        }

        // ================= ITEM tower =================
#pragma unroll
        for (int h = 0; h < 2; h++) {
            float acc1[2][8][4];
#pragma unroll
            for (int rb = 0; rb < 2; rb++)
#pragma unroll
                for (int i = 0; i < 8; i++)
#pragma unroll
                    for (int j = 0; j < 4; j++) acc1[rb][i][j] = 0.0f;
#pragma unroll
            for (int kt = 0; kt < 4; kt++) {
                uint32_t A0[4], A1[4];
                uint32_t chg = (uint32_t)(kt * 2 + khalf);
                ldm4(A0, sb + OFF_XFI + l0b + ((chg ^ l0x) << 4));
                ldm4(A1, sb + OFF_XFI + l1b + ((chg ^ l1x) << 4));
                uint32_t wb = sb + OFF_W1F + 16384u + ((uint32_t)((kt * 8 + h * 4) * 32 + lane)) * 16;
#pragma unroll
                for (int i = 0; i < 4; i++) {
                    uint32_t q[4];
                    lds128(q, wb + (uint32_t)i * 512);
                    mma_f16(acc1[0][2 * i],     A0, q[0], q[1]);
                    mma_f16(acc1[0][2 * i + 1], A0, q[2], q[3]);
                    mma_f16(acc1[1][2 * i],     A1, q[0], q[1]);
                    mma_f16(acc1[1][2 * i + 1], A1, q[2], q[3]);
                }
            }
            const float* b1p = (const float*)(smem + OFF_B1) + 128;
#pragma unroll
            for (int rb = 0; rb < 2; rb++)
#pragma unroll
                for (int kp = 0; kp < 4; kp++) {
                    int lA = 2 * kp, lB = 2 * kp + 1;
                    int cA = (8 * h + lA) * 8 + tg * 2, cB = (8 * h + lB) * 8 + tg * 2;
                    hfrag[rb][4 * h + kp][0] = packh2(fmaxf(acc1[rb][lA][0] + b1p[cA],     0.0f),
                                                     fmaxf(acc1[rb][lA][1] + b1p[cA + 1], 0.0f));
                    hfrag[rb][4 * h + kp][1] = packh2(fmaxf(acc1[rb][lA][2] + b1p[cA],     0.0f),
                                                     fmaxf(acc1[rb][lA][3] + b1p[cA + 1], 0.0f));
                    hfrag[rb][4 * h + kp][2] = packh2(fmaxf(acc1[rb][lB][0] + b1p[cB],     0.0f),
                                                     fmaxf(acc1[rb][lB][1] + b1p[cB + 1], 0.0f));
                    hfrag[rb][4 * h + kp][3] = packh2(fmaxf(acc1[rb][lB][2] + b1p[cB],     0.0f),
                                                     fmaxf(acc1[rb][lB][3] + b1p[cB + 1], 0.0f));
                }
        }
        // ---- GEMM2 item ----
#pragma unroll
        for (int rb = 0; rb < 2; rb++)
#pragma unroll
            for (int i = 0; i < 8; i++)
#pragma unroll
                for (int j = 0; j < 4; j++) acc2[rb][i][j] = 0.0f;
#pragma unroll
        for (int kt = 0; kt < 8; kt++) {
            uint32_t wb = sb + OFF_W2F + 16384u + ((uint32_t)(kt * 4 * 32 + lane)) * 16;
#pragma unroll
            for (int ntp = 0; ntp < 4; ntp++) {
                uint32_t q[4];
                lds128(q, wb + (uint32_t)ntp * 512);
                mma_f16(acc2[0][2 * ntp],     hfrag[0][kt], q[0], q[1]);
                mma_f16(acc2[0][2 * ntp + 1], hfrag[0][kt], q[2], q[3]);
                mma_f16(acc2[1][2 * ntp],     hfrag[1][kt], q[0], q[1]);
                mma_f16(acc2[1][2 * ntp + 1], hfrag[1][kt], q[2], q[3]);
            }
        }
        // ---- ep2 item: bias + relu + l2norm + dot(UVEC fp16) + store ----
        {
            const float* b2p = (const float*)(smem + OFF_B2) + 64;
#pragma unroll
            for (int rb = 0; rb < 2; rb++) {
                float ssA = 0.0f, ssB = 0.0f;
#pragma unroll
                for (int nt = 0; nt < 8; nt++) {
                    int c0 = nt * 8 + tg * 2;
                    acc2[rb][nt][0] = fmaxf(acc2[rb][nt][0] + b2p[c0],     0.0f);
                    acc2[rb][nt][1] = fmaxf(acc2[rb][nt][1] + b2p[c0 + 1], 0.0f);
                    acc2[rb][nt][2] = fmaxf(acc2[rb][nt][2] + b2p[c0],     0.0f);
                    acc2[rb][nt][3] = fmaxf(acc2[rb][nt][3] + b2p[c0 + 1], 0.0f);
                    ssA += acc2[rb][nt][0] * acc2[rb][nt][0] + acc2[rb][nt][1] * acc2[rb][nt][1];
                    ssB += acc2[rb][nt][2] * acc2[rb][nt][2] + acc2[rb][nt][3] * acc2[rb][nt][3];
                }
                ssA += __shfl_xor_sync(0xffffffffu, ssA, 1);
                ssA += __shfl_xor_sync(0xffffffffu, ssA, 2);
                ssB += __shfl_xor_sync(0xffffffffu, ssB, 1);
                ssB += __shfl_xor_sync(0xffffffffu, ssB, 2);
                float invA = 1.0f / fmaxf(sqrtf(ssA), 1e-12f);
                float invB = 1.0f / fmaxf(sqrtf(ssB), 1e-12f);
                float dA = 0.0f, dB = 0.0f;
                uint32_t base = (uint32_t)(((wid * 2 + rb) * 8) * 32 + lane) * 8u;
#pragma unroll
                for (int nt = 0; nt < 8; nt++) {
                    uint2 u = *(const uint2*)(smem + OFF_UVEC + base + (uint32_t)nt * 256u);
                    float2 uA = __half22float2(*(__half2*)&u.x);
                    float2 uB = __half22float2(*(__half2*)&u.y);
                    dA += uA.x * acc2[rb][nt][0] + uA.y * acc2[rb][nt][1];
                    dB += uB.x * acc2[rb][nt][2] + uB.y * acc2[rb][nt][3];
                }
                dA *= invA;
                dB *= invB;
                dA += __shfl_xor_sync(0xffffffffu, dA, 1);
                dA += __shfl_xor_sync(0xffffffffu, dA, 2);
                dB += __shfl_xor_sync(0xffffffffu, dB, 1);
                dB += __shfl_xor_sync(0xffffffffu, dB, 2);
                if (tg == 0) {
                    int r = rowbase + wrow0 + rb * 16 + g;
                    out[r]     = dA;
                    out[r + 8] = dB;
                }
            }
        }
        iid_hold = iid_next;
        __syncwarp();
    }
}

extern "C" void kernel_launch(void* const* d_in, const int* in_sizes, int n_in,
                              void* d_out, int out_size) {
    const int*   user_ids   = (const int*)d_in[0];
    const int*   item_ids   = (const int*)d_in[1];
    const float* user_table = (const float*)d_in[2];
    const float* item_table = (const float*)d_in[3];
    const float* uW1 = (const float*)d_in[4];
    const float* ub1 = (const float*)d_in[5];
    const float* uW2 = (const float*)d_in[6];
    const float* ub2 = (const float*)d_in[7];
    const float* iW1 = (const float*)d_in[8];
    const float* ib1 = (const float*)d_in[9];
    const float* iW2 = (const float*)d_in[10];
    const float* ib2 = (const float*)d_in[11];
    float* out = (float*)d_out;

    cudaFuncSetAttribute(twotower_kernel, cudaFuncAttributeMaxDynamicSharedMemorySize, SMEM_TOTAL);
    twotower_kernel<<<NCTAS, THREADS, SMEM_TOTAL>>>(
        user_ids, item_ids, user_table, item_table,
        uW1, ub1, uW2, ub2, iW1, ib1, iW2, ib2, out);
}

// round 13
// speedup vs baseline: 2.5420x; 1.0443x over previous
#include <cuda_runtime.h>
#include <cuda_fp16.h>
#include <cstdint>

// ============================================================================
// TwoTowerModel — independent-warp fp16 mma.sync, 32 rows/warp, register
// GEMM1->GEMM2 handoff, coalesced gather, fp16 VEC, warp-parity tower stagger,
// half2 epilogue-1. (baseline sm_103 ISA: no tcgen05)
// ============================================================================

static constexpr int BATCH   = 524288;
static constexpr int TILE    = 256;
static constexpr int NTILES  = BATCH / TILE;   // 2048
static constexpr int THREADS = 256;            // 8 warps x 32 rows
static constexpr int NCTAS   = 148;

// ---- shared memory layout (bytes) ----
static constexpr int OFF_XA   = 0;             // first-tower emb fp16 [256][64] swz, 32K
static constexpr int OFF_XB   = 32768;         // second-tower emb fp16, 32K
static constexpr int OFF_VEC  = 65536;         // first-tower normalized vec fp16, 32K
static constexpr int OFF_W1F  = 98304;         // W1 frags: [tower]*16K = 32K
static constexpr int OFF_W2F  = 131072;        // W2 frags: 32K
static constexpr int OFF_B1H  = 163840;        // half2[2][64] packed layer1 bias, 512B
static constexpr int OFF_B2   = 164352;        // float[2][64]
static constexpr int SMEM_TOTAL = 164864;

__device__ __forceinline__ uint32_t smem_u32(const void* p) {
    uint32_t a;
    asm("{ .reg .u64 t; cvta.to.shared.u64 t, %1; cvt.u32.u64 %0, t; }" : "=r"(a) : "l"(p));
    return a;
}
__device__ __forceinline__ void mma_f16(float* d, const uint32_t* a, uint32_t b0, uint32_t b1) {
    asm volatile("mma.sync.aligned.m16n8k16.row.col.f32.f16.f16.f32 "
        "{%0,%1,%2,%3}, {%4,%5,%6,%7}, {%8,%9}, {%0,%1,%2,%3};"
        : "+f"(d[0]), "+f"(d[1]), "+f"(d[2]), "+f"(d[3])
        : "r"(a[0]), "r"(a[1]), "r"(a[2]), "r"(a[3]), "r"(b0), "r"(b1));
}
__device__ __forceinline__ void ldm4(uint32_t* a, uint32_t addr) {
    asm volatile("ldmatrix.sync.aligned.m8n8.x4.shared.b16 {%0,%1,%2,%3}, [%4];"
        : "=r"(a[0]), "=r"(a[1]), "=r"(a[2]), "=r"(a[3]) : "r"(addr) : "memory");
}
__device__ __forceinline__ void lds128(uint32_t* q, uint32_t addr) {
    asm volatile("ld.shared.v4.b32 {%0,%1,%2,%3}, [%4];"
        : "=r"(q[0]), "=r"(q[1]), "=r"(q[2]), "=r"(q[3]) : "r"(addr));
}
__device__ __forceinline__ uint32_t packh2(float a, float b) {
    __half2 h = __floats2half2_rn(a, b);
    return *(uint32_t*)&h;
}
// cvt-pack + half2 bias-add + relu, returns packed fp16 pair
__device__ __forceinline__ uint32_t ep1h2(float a, float b, uint32_t bias2) {
    __half2 x = __floats2half2_rn(a, b);
    x = __hmax2(__hadd2(x, *(__half2*)&bias2), __half2(__float2half_rn(0.0f), __float2half_rn(0.0f)));
    return *(uint32_t*)&x;
}

__global__ __launch_bounds__(THREADS, 1)
void twotower_kernel(
    const int* __restrict__ user_ids, const int* __restrict__ item_ids,
    const float* __restrict__ user_table, const float* __restrict__ item_table,
    const float* __restrict__ uW1, const float* __restrict__ ub1,
    const float* __restrict__ uW2, const float* __restrict__ ub2,
    const float* __restrict__ iW1, const float* __restrict__ ib1,
    const float* __restrict__ iW2, const float* __restrict__ ib2,
    float* __restrict__ out)
{
    extern __shared__ char smem[];
    const uint32_t sb = smem_u32(smem);
    const int tid  = threadIdx.x;
    const int wid  = tid >> 5;
    const int lane = tid & 31;
    const int tg   = lane & 3;
    const int g    = lane >> 2;
    const int khalf = lane >> 4;

    // ============ stage weights as nt-paired mma B-fragments (fp16) ====
    for (int t = 0; t < 2; t++) {
        const float* gW1 = t ? iW1 : uW1;   // [64][128] row-major
        const float* gW2 = t ? iW2 : uW2;   // [128][64]
        const float* gb1 = t ? ib1 : ub1;
        const float* gb2 = t ? ib2 : ub2;
        for (int p = tid; p < 1024; p += THREADS) {       // W1: kt(4) x ntp(8) x lane(32)
            int kt = p >> 8, ntp = (p >> 5) & 7, ln = p & 31;
            int ltg = ln & 3, lg = ln >> 2;
            int k0 = kt * 16 + ltg * 2;
            uint32_t q[4];
#pragma unroll
            for (int s = 0; s < 2; s++) {
                int n = (2 * ntp + s) * 8 + lg;
                q[2 * s + 0] = packh2(__ldg(gW1 + k0 * 128 + n),       __ldg(gW1 + (k0 + 1) * 128 + n));
                q[2 * s + 1] = packh2(__ldg(gW1 + (k0 + 8) * 128 + n), __ldg(gW1 + (k0 + 9) * 128 + n));
            }
            *((uint4*)(smem + OFF_W1F + t * 16384) + p) = make_uint4(q[0], q[1], q[2], q[3]);
        }
        for (int p = tid; p < 1024; p += THREADS) {       // W2: kt(8) x ntp(4) x lane(32)
            int kt = p >> 7, ntp = (p >> 5) & 3, ln = p & 31;
            int ltg = ln & 3, lg = ln >> 2;
            int k0 = kt * 16 + ltg * 2;
            uint32_t q[4];
#pragma unroll
            for (int s = 0; s < 2; s++) {
                int n = (2 * ntp + s) * 8 + lg;
                q[2 * s + 0] = packh2(__ldg(gW2 + k0 * 64 + n),       __ldg(gW2 + (k0 + 1) * 64 + n));
                q[2 * s + 1] = packh2(__ldg(gW2 + (k0 + 8) * 64 + n), __ldg(gW2 + (k0 + 9) * 64 + n));
            }
            *((uint4*)(smem + OFF_W2F + t * 16384) + p) = make_uint4(q[0], q[1], q[2], q[3]);
        }
        if (tid < 64) {   // packed half2 layer-1 bias: idx = nt*4+tg -> (b[c0], b[c0+1])
            int nt = tid >> 2, ltg = tid & 3;
            int c0 = nt * 8 + ltg * 2;
            ((uint32_t*)(smem + OFF_B1H))[t * 64 + tid] = packh2(__ldg(gb1 + c0), __ldg(gb1 + c0 + 1));
        }
        if (tid < 64)  ((float*)(smem + OFF_B2))[t * 64 + tid] = __ldg(gb2 + tid);
    }
    __syncthreads();

    const int pf = wid & 1;                   // parity: which tower goes first
    const int* idsF = pf ? item_ids : user_ids;
    const int* idsS = pf ? user_ids : item_ids;
    const float* tblF = pf ? item_table : user_table;
    const float* tblS = pf ? user_table : item_table;
    const uint32_t wofF = pf ? 16384u : 0u;
    const uint32_t wofS = 16384u - wofF;
    const uint32_t b1hF = (uint32_t)pf * 256u, b1hS = 256u - b1hF;
    const int b2F = pf * 64, b2S = 64 - b2F;

    const int wrow0 = wid * 32;               // warp's 32-row slab base
    const int myrow = wrow0 + lane;           // id-resident row (1 id/lane)
    const int rg = lane >> 3;                 // coalesced gather: row-in-group-of-4
    const int gs = lane & 7;                  // 16B sector within 128B line
    const int lr0 = wrow0 + (lane & 15);      // ldmatrix source rows
    const int lr1 = lr0 + 16;
    const uint32_t l0b = (uint32_t)lr0 * 128, l1b = (uint32_t)lr1 * 128;
    const uint32_t l0x = (uint32_t)(lr0 & 7), l1x = (uint32_t)(lr1 & 7);

    // ---------------- prologue: stage tile0 first-tower rows + second id ----
    int tile = blockIdx.x;
    float4 stg[16];
    {
        int idf = __ldg(idsF + tile * TILE + myrow);
#pragma unroll
        for (int k = 0; k < 8; k++) {
            int idk = __shfl_sync(0xffffffffu, idf, k * 4 + rg);
            const float4* src = (const float4*)(tblF + (size_t)(uint32_t)idk * 64);
            stg[k]     = __ldg(src + gs);
            stg[k + 8] = __ldg(src + 8 + gs);
        }
    }
    int idS_hold = __ldg(idsS + tile * TILE + myrow);

    for (; tile < NTILES; tile += gridDim.x) {
        const int rowbase = tile * TILE;
        int tnext = tile + (int)gridDim.x;
        if (tnext >= NTILES) tnext = tile;    // harmless reload on last iteration

        // ---- 1. convert staged first-tower rows -> XA ----
#pragma unroll
        for (int j = 0; j < 16; j++) {
            int k = j & 7, half = j >> 3;
            int r = wrow0 + k * 4 + rg;
            float4 v = stg[half * 8 + k];
            uint32_t chunk = (uint32_t)(half * 4 + (gs >> 1));
            uint32_t ad = (uint32_t)r * 128 + ((chunk ^ (uint32_t)(r & 7)) << 4) + (uint32_t)(gs & 1) * 8;
            *(uint2*)(smem + OFF_XA + ad) = make_uint2(packh2(v.x, v.y), packh2(v.z, v.w));
        }
        __syncwarp();

        // ---- 2. issue second-tower gather ----
#pragma unroll
        for (int k = 0; k < 8; k++) {
            int idk = __shfl_sync(0xffffffffu, idS_hold, k * 4 + rg);
            const float4* src = (const float4*)(tblS + (size_t)(uint32_t)idk * 64);
            stg[k]     = __ldg(src + gs);
            stg[k + 8] = __ldg(src + 8 + gs);
        }
        // ---- 3. prefetch next-tile ids ----
        int idF_next = __ldg(idsF + tnext * TILE + myrow);
        int idS_next = __ldg(idsS + tnext * TILE + myrow);

        uint32_t hfrag[2][8][4];
        float acc2[2][8][4];

        // ================= FIRST tower =================
#pragma unroll
        for (int h = 0; h < 2; h++) {
            float acc1[2][8][4];
#pragma unroll
            for (int rb = 0; rb < 2; rb++)
#pragma unroll
                for (int i = 0; i < 8; i++)
#pragma unroll
                    for (int j = 0; j < 4; j++) acc1[rb][i][j] = 0.0f;
#pragma unroll
            for (int kt = 0; kt < 4; kt++) {
                uint32_t A0[4], A1[4];
                uint32_t chg = (uint32_t)(kt * 2 + khalf);
                ldm4(A0, sb + OFF_XA + l0b + ((chg ^ l0x) << 4));
                ldm4(A1, sb + OFF_XA + l1b + ((chg ^ l1x) << 4));
                uint32_t wb = sb + OFF_W1F + wofF + ((uint32_t)((kt * 8 + h * 4) * 32 + lane)) * 16;
#pragma unroll
                for (int i = 0; i < 4; i++) {
                    uint32_t q[4];
                    lds128(q, wb + (uint32_t)i * 512);
                    mma_f16(acc1[0][2 * i],     A0, q[0], q[1]);
                    mma_f16(acc1[0][2 * i + 1], A0, q[2], q[3]);
                    mma_f16(acc1[1][2 * i],     A1, q[0], q[1]);
                    mma_f16(acc1[1][2 * i + 1], A1, q[2], q[3]);
                }
            }
            // ep1 (half2): bias+relu -> hfrag (GEMM2 A-frags, in-register)
            const uint32_t* b1p = (const uint32_t*)(smem + OFF_B1H + b1hF);
#pragma unroll
            for (int rb = 0; rb < 2; rb++)
#pragma unroll
                for (int kp = 0; kp < 4; kp++) {
                    int lA = 2 * kp, lB = 2 * kp + 1;
                    uint32_t bA = b1p[(8 * h + lA) * 4 + tg];
                    uint32_t bB = b1p[(8 * h + lB) * 4 + tg];
                    hfrag[rb][4 * h + kp][0] = ep1h2(acc1[rb][lA][0], acc1[rb][lA][1], bA);
                    hfrag[rb][4 * h + kp][1] = ep1h2(acc1[rb][lA][2], acc1[rb][lA][3], bA);
                    hfrag[rb][4 * h + kp][2] = ep1h2(acc1[rb][lB][0], acc1[rb][lB][1], bB);
                    hfrag[rb][4 * h + kp][3] = ep1h2(acc1[rb][lB][2], acc1[rb][lB][3], bB);
                }
        }
        // ---- GEMM2 first ----
#pragma unroll
        for (int rb = 0; rb < 2; rb++)
#pragma unroll
            for (int i = 0; i < 8; i++)
#pragma unroll
                for (int j = 0; j < 4; j++) acc2[rb][i][j] = 0.0f;
#pragma unroll
        for (int kt = 0; kt < 8; kt++) {
            uint32_t wb = sb + OFF_W2F + wofF + ((uint32_t)(kt * 4 * 32 + lane)) * 16;
#pragma unroll
            for (int ntp = 0; ntp < 4; ntp++) {
                uint32_t q[4];
                lds128(q, wb + (uint32_t)ntp * 512);
                mma_f16(acc2[0][2 * ntp],     hfrag[0][kt], q[0], q[1]);
                mma_f16(acc2[0][2 * ntp + 1], hfrag[0][kt], q[2], q[3]);
                mma_f16(acc2[1][2 * ntp],     hfrag[1][kt], q[0], q[1]);
                mma_f16(acc2[1][2 * ntp + 1], hfrag[1][kt], q[2], q[3]);
            }
        }
        // ---- ep2 first: bias + relu + l2norm -> VEC (fp16 frag-linear) ----
        {
            const float* b2p = (const float*)(smem + OFF_B2) + b2F;
#pragma unroll
            for (int rb = 0; rb < 2; rb++) {
                float ssA = 0.0f, ssB = 0.0f;
#pragma unroll
                for (int nt = 0; nt < 8; nt++) {
                    int c0 = nt * 8 + tg * 2;
                    acc2[rb][nt][0] = fmaxf(acc2[rb][nt][0] + b2p[c0],     0.0f);
                    acc2[rb][nt][1] = fmaxf(acc2[rb][nt][1] + b2p[c0 + 1], 0.0f);
                    acc2[rb][nt][2] = fmaxf(acc2[rb][nt][2] + b2p[c0],     0.0f);
                    acc2[rb][nt][3] = fmaxf(acc2[rb][nt][3] + b2p[c0 + 1], 0.0f);
                    ssA += acc2[rb][nt][0] * acc2[rb][nt][0] + acc2[rb][nt][1] * acc2[rb][nt][1];
                    ssB += acc2[rb][nt][2] * acc2[rb][nt][2] + acc2[rb][nt][3] * acc2[rb][nt][3];
                }
                ssA += __shfl_xor_sync(0xffffffffu, ssA, 1);
                ssA += __shfl_xor_sync(0xffffffffu, ssA, 2);
                ssB += __shfl_xor_sync(0xffffffffu, ssB, 1);
                ssB += __shfl_xor_sync(0xffffffffu, ssB, 2);
                float invA = 1.0f / fmaxf(sqrtf(ssA), 1e-12f);
                float invB = 1.0f / fmaxf(sqrtf(ssB), 1e-12f);
                uint32_t base = (uint32_t)(((wid * 2 + rb) * 8) * 32 + lane) * 8u;
#pragma unroll
                for (int nt = 0; nt < 8; nt++) {
                    uint2 v = make_uint2(packh2(acc2[rb][nt][0] * invA, acc2[rb][nt][1] * invA),
                                         packh2(acc2[rb][nt][2] * invB, acc2[rb][nt][3] * invB));
                    *(uint2*)(smem + OFF_VEC + base + (uint32_t)nt * 256u) = v;
                }
            }
        }
        __syncwarp();

        // ---- 5. convert second-tower rows -> XB; staging freed ----
#pragma unroll
        for (int j = 0; j < 16; j++) {
            int k = j & 7, half = j >> 3;
            int r = wrow0 + k * 4 + rg;
            float4 v = stg[half * 8 + k];
            uint32_t chunk = (uint32_t)(half * 4 + (gs >> 1));
            uint32_t ad = (uint32_t)r * 128 + ((chunk ^ (uint32_t)(r & 7)) << 4) + (uint32_t)(gs & 1) * 8;
            *(uint2*)(smem + OFF_XB + ad) = make_uint2(packh2(v.x, v.y), packh2(v.z, v.w));
        }
        __syncwarp();

        // ---- 6. issue next-tile first-tower gather ----
#pragma unroll
        for (int k = 0; k < 8; k++) {
            int idk = __shfl_sync(0xffffffffu, idF_next, k * 4 + rg);
            const float4* src = (const float4*)(tblF + (size_t)(uint32_t)idk * 64);
            stg[k]     = __ldg(src + gs);
            stg[k + 8] = __ldg(src + 8 + gs);
        }

        // ================= SECOND tower =================
#pragma unroll
        for (int h = 0; h < 2; h++) {
            float acc1[2][8][4];
#pragma unroll
            for (int rb = 0; rb < 2; rb++)
#pragma unroll
                for (int i = 0; i < 8; i++)
#pragma unroll
                    for (int j = 0; j < 4; j++) acc1[rb][i][j] = 0.0f;
#pragma unroll
            for (int kt = 0; kt < 4; kt++) {
                uint32_t A0[4], A1[4];
                uint32_t chg = (uint32_t)(kt * 2 + khalf);
                ldm4(A0, sb + OFF_XB + l0b + ((chg ^ l0x) << 4));
                ldm4(A1, sb + OFF_XB + l1b + ((chg ^ l1x) << 4));
                uint32_t wb = sb + OFF_W1F + wofS + ((uint32_t)((kt * 8 + h * 4) * 32 + lane)) * 16;
#pragma unroll
                for (int i = 0; i < 4; i++) {
                    uint32_t q[4];
                    lds128(q, wb + (uint32_t)i * 512);
                    mma_f16(acc1[0][2 * i],     A0, q[0], q[1]);
                    mma_f16(acc1[0][2 * i + 1], A0, q[2], q[3]);
                    mma_f16(acc1[1][2 * i],     A1, q[0], q[1]);
                    mma_f16(acc1[1][2 * i + 1], A1, q[2], q[3]);
                }
            }
            const uint32_t* b1p = (const uint32_t*)(smem + OFF_B1H + b1hS);
#pragma unroll
            for (int rb = 0; rb < 2; rb++)
#pragma unroll
                for (int kp = 0; kp < 4; kp++) {
                    int lA = 2 * kp, lB = 2 * kp + 1;
                    uint32_t bA = b1p[(8 * h + lA) * 4 + tg];
                    uint32_t bB = b1p[(8 * h + lB) * 4 + tg];
                    hfrag[rb][4 * h + kp][0] = ep1h2(acc1[rb][lA][0], acc1[rb][lA][1], bA);
                    hfrag[rb][4 * h + kp][1] = ep1h2(acc1[rb][lA][2], acc1[rb][lA][3], bA);
                    hfrag[rb][4 * h + kp][2] = ep1h2(acc1[rb][lB][0], acc1[rb][lB][1], bB);
                    hfrag[rb][4 * h + kp][3] = ep1h2(acc1[rb][lB][2], acc1[rb][lB][3], bB);
                }
        }
        // ---- GEMM2 second ----
#pragma unroll
        for (int rb = 0; rb < 2; rb++)
#pragma unroll
            for (int i = 0; i < 8; i++)
#pragma unroll
                for (int j = 0; j < 4; j++) acc2[rb][i][j] = 0.0f;
#pragma unroll
        for (int kt = 0; kt < 8; kt++) {
            uint32_t wb = sb + OFF_W2F + wofS + ((uint32_t)(kt * 4 * 32 + lane)) * 16;
#pragma unroll
            for (int ntp = 0; ntp < 4; ntp++) {
                uint32_t q[4];
                lds128(q, wb + (uint32_t)ntp * 512);
                mma_f16(acc2[0][2 * ntp],     hfrag[0][kt], q[0], q[1]);
                mma_f16(acc2[0][2 * ntp + 1], hfrag[0][kt], q[2], q[3]);
                mma_f16(acc2[1][2 * ntp],     hfrag[1][kt], q[0], q[1]);
                mma_f16(acc2[1][2 * ntp + 1], hfrag[1][kt], q[2], q[3]);
            }
        }
        // ---- ep2 second: bias + relu + l2norm + dot(VEC fp16) + store ----
        {
            const float* b2p = (const float*)(smem + OFF_B2) + b2S;
#pragma unroll
            for (int rb = 0; rb < 2; rb++) {
                float ssA = 0.0f, ssB = 0.0f;
#pragma unroll
                for (int nt = 0; nt < 8; nt++) {
                    int c0 = nt * 8 + tg * 2;
                    acc2[rb][nt][0] = fmaxf(acc2[rb][nt][0] + b2p[c0],     0.0f);
                    acc2[rb][nt][1] = fmaxf(acc2[rb][nt][1] + b2p[c0 + 1], 0.0f);
                    acc2[rb][nt][2] = fmaxf(acc2[rb][nt][2] + b2p[c0],     0.0f);
                    acc2[rb][nt][3] = fmaxf(acc2[rb][nt][3] + b2p[c0 + 1], 0.0f);
                    ssA += acc2[rb][nt][0] * acc2[rb][nt][0] + acc2[rb][nt][1] * acc2[rb][nt][1];
                    ssB += acc2[rb][nt][2] * acc2[rb][nt][2] + acc2[rb][nt][3] * acc2[rb][nt][3];
                }
                ssA += __shfl_xor_sync(0xffffffffu, ssA, 1);
                ssA += __shfl_xor_sync(0xffffffffu, ssA, 2);
                ssB += __shfl_xor_sync(0xffffffffu, ssB, 1);
                ssB += __shfl_xor_sync(0xffffffffu, ssB, 2);
                float invA = 1.0f / fmaxf(sqrtf(ssA), 1e-12f);
                float invB = 1.0f / fmaxf(sqrtf(ssB), 1e-12f);
                float dA = 0.0f, dB = 0.0f;
                uint32_t base = (uint32_t)(((wid * 2 + rb) * 8) * 32 + lane) * 8u;
#pragma unroll
                for (int nt = 0; nt < 8; nt++) {
                    uint2 u = *(const uint2*)(smem + OFF_VEC + base + (uint32_t)nt * 256u);
                    float2 uA = __half22float2(*(__half2*)&u.x);
                    float2 uB = __half22float2(*(__half2*)&u.y);
                    dA += uA.x * acc2[rb][nt][0] + uA.y * acc2[rb][nt][1];
                    dB += uB.x * acc2[rb][nt][2] + uB.y * acc2[rb][nt][3];
                }
                dA *= invA;
                dB *= invB;
                dA += __shfl_xor_sync(0xffffffffu, dA, 1);
                dA += __shfl_xor_sync(0xffffffffu, dA, 2);
                dB += __shfl_xor_sync(0xffffffffu, dB, 1);
                dB += __shfl_xor_sync(0xffffffffu, dB, 2);
                if (tg == 0) {
                    int r = rowbase + wrow0 + rb * 16 + g;
                    out[r]     = dA;
                    out[r + 8] = dB;
                }
            }
        }
        idS_hold = idS_next;
        __syncwarp();
    }
}

extern "C" void kernel_launch(void* const* d_in, const int* in_sizes, int n_in,
                              void* d_out, int out_size) {
    const int*   user_ids   = (const int*)d_in[0];
    const int*   item_ids   = (const int*)d_in[1];
    const float* user_table = (const float*)d_in[2];
    const float* item_table = (const float*)d_in[3];
    const float* uW1 = (const float*)d_in[4];
    const float* ub1 = (const float*)d_in[5];
    const float* uW2 = (const float*)d_in[6];
    const float* ub2 = (const float*)d_in[7];
    const float* iW1 = (const float*)d_in[8];
    const float* ib1 = (const float*)d_in[9];
    const float* iW2 = (const float*)d_in[10];
    const float* ib2 = (const float*)d_in[11];
    float* out = (float*)d_out;

    cudaFuncSetAttribute(twotower_kernel, cudaFuncAttributeMaxDynamicSharedMemorySize, SMEM_TOTAL);
    twotower_kernel<<<NCTAS, THREADS, SMEM_TOTAL>>>(
        user_ids, item_ids, user_table, item_table,
        uW1, ub1, uW2, ub2, iW1, ib1, iW2, ib2, out);
}